// round 2
// baseline (speedup 1.0000x reference)
#include <cuda_runtime.h>
#include <math.h>

#define H 512
#define B 32
#define T 32
#define V 6000
#define NS 6

// ---------------- scratch buffer layout (floats) ----------------
#define SZ_ROWHB (T*B*H)                 // 524288
#define OFF_XEMB 0
#define OFF_G0   (OFF_XEMB + SZ_ROWHB)   // [t][b][4H]
#define OFF_DOUT (OFF_G0 + T*B*4*H)      // [t][b][H]
#define OFF_NORM (OFF_DOUT + SZ_ROWHB)
#define OFF_ERAW (OFF_NORM + SZ_ROWHB)   // [b][t][H]
#define OFF_EOUT (OFF_ERAW + SZ_ROWHB)   // [b][t][H]
#define OFF_KPRE (OFF_EOUT + SZ_ROWHB)   // [b][t][H]
#define OFF_CTX  (OFF_KPRE + SZ_ROWHB)
#define OFF_DH0  (OFF_CTX + B*H)
#define OFF_DH1  (OFF_DH0 + 2*B*H)
#define OFF_DC0  (OFF_DH1 + 2*B*H)
#define OFF_DC1  (OFF_DC0 + B*H)
#define OFF_EH0  (OFF_DC1 + B*H)
#define OFF_EH1  (OFF_EH0 + 2*B*H)
#define OFF_EC0  (OFF_EH1 + 2*B*H)
#define OFF_EC1  (OFF_EC0 + B*H)
#define OFF_PACK (OFF_EC1 + B*H)
#define PACK_SZ  (H*H*4)
#define N_PACK   7
#define BUF_TOTAL (OFF_PACK + (size_t)N_PACK*PACK_SZ)
#define ZERO_CNT (OFF_PACK - OFF_CTX)    // 212992

__device__ float g_buf[BUF_TOTAL];
__device__ int   g_mask[B*T];

// ---------------- zero recurrent state ----------------
__global__ void k_zero() {
    int i = blockIdx.x * 256 + threadIdx.x;
    if (i < ZERO_CNT) g_buf[OFF_CTX + i] = 0.0f;
}

// ---------------- pack gate weights [4H x ldw] -> [j][k][ifgo] float4 ----------------
__global__ void k_pack(const float* __restrict__ W, int ldw, float* __restrict__ P, int K) {
    int j = blockIdx.y;
    int k = blockIdx.x * 128 + threadIdx.x;
    float4 v;
    v.x = W[(size_t)(0*H + j) * ldw + k];
    v.y = W[(size_t)(1*H + j) * ldw + k];
    v.z = W[(size_t)(2*H + j) * ldw + k];
    v.w = W[(size_t)(3*H + j) * ldw + k];
    ((float4*)P)[(size_t)j * K + k] = v;
}

// ---------------- embedding gather (builds dec_in / enc tokens on the fly) ----------------
__global__ void k_gather(const int* __restrict__ inputs, const int* __restrict__ targets,
                         const float* __restrict__ emb, float* __restrict__ X,
                         int s, int is_dec) {
    int row = blockIdx.x;          // t*32 + b
    int t = row >> 5, b = row & 31;
    int tok;
    if (is_dec) {
        if (t == 0) tok = 1; // SOS
        else tok = (s == 0) ? inputs[b*192 + (t-1)] : targets[b*160 + (s-1)*32 + (t-1)];
    } else {
        tok = (s == 0) ? inputs[b*192 + t] : targets[b*160 + (s-1)*32 + t];
    }
    const float* e = emb + (size_t)tok * H;
    float* o = X + (size_t)row * H;
    for (int i = threadIdx.x; i < H; i += 128) o[i] = e[i];
}

// ---------------- mask for next sentence ----------------
__global__ void k_maskk(const int* __restrict__ inputs, const int* __restrict__ targets, int s) {
    int b = threadIdx.x;
    if (b >= B) return;
    int seen = 0;
    for (int t = 0; t < T; t++) {
        g_mask[b*T + t] = seen;
        int tok = (s == 0) ? inputs[b*192 + t] : targets[b*160 + (s-1)*32 + t];
        if (tok == 2 || tok == 3) seen = 1;
    }
}

// ---------------- generic tiled SGEMM: C[M=1024, N] = A[1024,K] @ W[N,ldw]^T + bias ----------------
// mode 0: C[m*N+n]   mode 1: logits remap into out[b][s-1][t][n]
__global__ void k_gemm(const float* __restrict__ A, int lda,
                       const float* __restrict__ W, int ldw,
                       const float* __restrict__ bias,
                       float* __restrict__ C, int N, int K, int mode, int s) {
    __shared__ float As[16][68];
    __shared__ float Bs[16][68];
    int tid = threadIdx.x;
    int m0 = blockIdx.y * 64, n0 = blockIdx.x * 64;
    int lr = tid >> 2, lc = (tid & 3) * 4;
    int ty = tid >> 4, tx = tid & 15;
    float acc[4][4] = {};
    for (int k0 = 0; k0 < K; k0 += 16) {
        float4 av = *(const float4*)(A + (size_t)(m0 + lr) * lda + k0 + lc);
        float4 bv = make_float4(0.f, 0.f, 0.f, 0.f);
        if (n0 + lr < N) bv = *(const float4*)(W + (size_t)(n0 + lr) * ldw + k0 + lc);
        __syncthreads();
        As[lc+0][lr] = av.x; As[lc+1][lr] = av.y; As[lc+2][lr] = av.z; As[lc+3][lr] = av.w;
        Bs[lc+0][lr] = bv.x; Bs[lc+1][lr] = bv.y; Bs[lc+2][lr] = bv.z; Bs[lc+3][lr] = bv.w;
        __syncthreads();
        #pragma unroll
        for (int k = 0; k < 16; k++) {
            float4 a = *(const float4*)&As[k][ty*4];
            float4 b = *(const float4*)&Bs[k][tx*4];
            acc[0][0] += a.x*b.x; acc[0][1] += a.x*b.y; acc[0][2] += a.x*b.z; acc[0][3] += a.x*b.w;
            acc[1][0] += a.y*b.x; acc[1][1] += a.y*b.y; acc[1][2] += a.y*b.z; acc[1][3] += a.y*b.w;
            acc[2][0] += a.z*b.x; acc[2][1] += a.z*b.y; acc[2][2] += a.z*b.z; acc[2][3] += a.z*b.w;
            acc[3][0] += a.w*b.x; acc[3][1] += a.w*b.y; acc[3][2] += a.w*b.z; acc[3][3] += a.w*b.w;
        }
    }
    #pragma unroll
    for (int i = 0; i < 4; i++)
        #pragma unroll
        for (int j = 0; j < 4; j++) {
            int m = m0 + ty*4 + i, n = n0 + tx*4 + j;
            if (n < N) {
                float v = acc[i][j] + (bias ? bias[n] : 0.f);
                if (mode == 0) C[(size_t)m * N + n] = v;
                else {
                    int t = m >> 5, b = m & 31;
                    C[(((size_t)b*5 + (s-1))*32 + t) * V + n] = v;
                }
            }
        }
}

// ---------------- fused LSTM layer step ----------------
// gates[b][g*H+j] = base + X1[b,:]·W1packed + X2[b,:]·W2packed  -> c,h update
__global__ void k_lstm(const float* __restrict__ base, int base_vec,
                       const float* __restrict__ X1, const float* __restrict__ P1, int K1,
                       const float* __restrict__ X2, const float* __restrict__ P2, int K2,
                       float* __restrict__ cst, float* __restrict__ hout,
                       float* __restrict__ store, int store_bstride) {
    __shared__ float Xs[64*33];
    int tid = threadIdx.x;
    int warp = tid >> 5, lane = tid & 31;           // lane = batch
    int j = blockIdx.x * 4 + warp;                  // hidden unit
    float gi, gf, gg, go;
    if (base_vec) { gi = base[j]; gf = base[H+j]; gg = base[2*H+j]; go = base[3*H+j]; }
    else {
        const float* r = base + (size_t)lane * (4*H);
        gi = r[j]; gf = r[H+j]; gg = r[2*H+j]; go = r[3*H+j];
    }
    for (int src = 0; src < 2; src++) {
        const float* X = src ? X2 : X1;
        const float* P = src ? P2 : P1;
        int K = src ? K2 : K1;
        if (K == 0) continue;
        const float4* Pj = (const float4*)P + (size_t)j * K;
        for (int k0 = 0; k0 < K; k0 += 64) {
            __syncthreads();
            for (int i = tid; i < 32*64; i += 128) {
                int bb = i >> 6, kk = i & 63;
                Xs[kk*33 + bb] = X[(size_t)bb*K + k0 + kk];
            }
            __syncthreads();
            #pragma unroll 8
            for (int kk = 0; kk < 64; kk++) {
                float x = Xs[kk*33 + lane];
                float4 w = Pj[k0 + kk];
                gi += x*w.x; gf += x*w.y; gg += x*w.z; go += x*w.w;
            }
        }
    }
    float c  = cst[lane*H + j];
    float si = 1.f / (1.f + expf(-gi));
    float sf = 1.f / (1.f + expf(-gf));
    float so = 1.f / (1.f + expf(-go));
    float c2 = sf * c + si * tanhf(gg);
    float h2 = so * tanhf(c2);
    cst[lane*H + j]  = c2;
    hout[lane*H + j] = h2;
    if (store) store[(size_t)lane*store_bstride + j] = h2;
}

// ---------------- attention (one block per batch row) ----------------
__global__ void k_attn(const float* __restrict__ h1, const float* __restrict__ Kpre,
                       const float* __restrict__ enc_outs, const float* __restrict__ attW,
                       const float* __restrict__ attv, float* __restrict__ ctx) {
    int b = blockIdx.x, tid = threadIdx.x;
    __shared__ float h1s[H];
    __shared__ float qW[H];
    __shared__ float sc[T];
    h1s[tid]       = h1[b*H + tid];
    h1s[tid + 256] = h1[b*H + tid + 256];
    __syncthreads();
    #pragma unroll
    for (int jj = 0; jj < 2; jj++) {
        int j = tid + jj*256;
        const float4* row = (const float4*)(attW + (size_t)j * (2*H));
        const float4* hh  = (const float4*)h1s;
        float acc = 0.f;
        #pragma unroll 4
        for (int k = 0; k < H/4; k++) {
            float4 w = row[k], x = hh[k];
            acc += w.x*x.x + w.y*x.y + w.z*x.z + w.w*x.w;
        }
        qW[j] = acc;
    }
    __syncthreads();
    int warp = tid >> 5, lane = tid & 31;
    for (int t = warp; t < T; t += 8) {
        if (g_mask[b*T + t]) { if (lane == 0) sc[t] = -1e9f; continue; }
        float p = 0.f;
        const float* kp = Kpre + ((size_t)b*T + t) * H;
        for (int j = lane; j < H; j += 32) p += tanhf(qW[j] + kp[j]) * attv[j];
        for (int o = 16; o; o >>= 1) p += __shfl_xor_sync(0xffffffffu, p, o);
        if (lane == 0) sc[t] = p;
    }
    __syncthreads();
    if (tid < 32) {
        float v = sc[tid];
        float m = v;
        for (int o = 16; o; o >>= 1) m = fmaxf(m, __shfl_xor_sync(0xffffffffu, m, o));
        float e = expf(v - m);
        float ssum = e;
        for (int o = 16; o; o >>= 1) ssum += __shfl_xor_sync(0xffffffffu, ssum, o);
        sc[tid] = e / ssum;
    }
    __syncthreads();
    #pragma unroll
    for (int jj = 0; jj < 2; jj++) {
        int hc = tid + jj*256;
        float acc = 0.f;
        const float* eo = enc_outs + (size_t)b*T*H + hc;
        #pragma unroll
        for (int t = 0; t < T; t++) acc += sc[t] * eo[(size_t)t*H];
        ctx[b*H + hc] = acc;
    }
}

// ---------------- layernorm over H, one block per row ----------------
__global__ void k_ln(const float* __restrict__ in, float* __restrict__ out,
                     const float* __restrict__ g, const float* __restrict__ bb) {
    int row = blockIdx.x, tid = threadIdx.x;   // 128 threads
    const float* x = in + (size_t)row * H;
    float v[4], s = 0.f;
    #pragma unroll
    for (int i = 0; i < 4; i++) { v[i] = x[tid + i*128]; s += v[i]; }
    __shared__ float rs[4];
    for (int o = 16; o; o >>= 1) s += __shfl_xor_sync(0xffffffffu, s, o);
    int warp = tid >> 5, lane = tid & 31;
    if (lane == 0) rs[warp] = s;
    __syncthreads();
    float mean = (rs[0] + rs[1] + rs[2] + rs[3]) / (float)H;
    __syncthreads();
    float s2 = 0.f;
    #pragma unroll
    for (int i = 0; i < 4; i++) { float d = v[i] - mean; s2 += d*d; }
    for (int o = 16; o; o >>= 1) s2 += __shfl_xor_sync(0xffffffffu, s2, o);
    if (lane == 0) rs[warp] = s2;
    __syncthreads();
    float var = (rs[0] + rs[1] + rs[2] + rs[3]) / (float)H;
    float inv = rsqrtf(var + 1e-5f);
    #pragma unroll
    for (int i = 0; i < 4; i++) {
        int c = tid + i*128;
        out[(size_t)row*H + c] = (v[i] - mean) * inv * g[c] + bb[c];
    }
}

// ---------------- host orchestration ----------------
extern "C" void kernel_launch(void* const* d_in, const int* in_sizes, int n_in,
                              void* d_out, int out_size) {
    const int*   inputs   = (const int*)d_in[0];
    const int*   targets  = (const int*)d_in[1];
    const float* enc_emb  = (const float*)d_in[2];
    const float* enc_Wih  = (const float*)d_in[3];
    const float* enc_Whh  = (const float*)d_in[4];
    const float* enc_bias = (const float*)d_in[5];
    const float* enc_ln_g = (const float*)d_in[6];
    const float* enc_ln_b = (const float*)d_in[7];
    const float* dec_emb  = (const float*)d_in[8];
    const float* att_W    = (const float*)d_in[9];
    const float* att_b    = (const float*)d_in[10];
    const float* att_v    = (const float*)d_in[11];
    const float* dec_Wih0 = (const float*)d_in[12];
    const float* dec_Wih1 = (const float*)d_in[13];
    const float* dec_Whh  = (const float*)d_in[14];
    const float* dec_bias = (const float*)d_in[15];
    const float* dec_ln_g = (const float*)d_in[16];
    const float* dec_ln_b = (const float*)d_in[17];
    const float* fc_W     = (const float*)d_in[18];
    const float* fc_b     = (const float*)d_in[19];
    float* out = (float*)d_out;

    float* buf = nullptr;
    cudaGetSymbolAddress((void**)&buf, g_buf);

    float* Xemb = buf + OFF_XEMB;
    float* G0   = buf + OFF_G0;
    float* Dout = buf + OFF_DOUT;
    float* Norm = buf + OFF_NORM;
    float* Eraw = buf + OFF_ERAW;
    float* Eout = buf + OFF_EOUT;
    float* Kpre = buf + OFF_KPRE;
    float* Ctx  = buf + OFF_CTX;
    float* DH0  = buf + OFF_DH0;
    float* DH1  = buf + OFF_DH1;
    float* DC0  = buf + OFF_DC0;
    float* DC1  = buf + OFF_DC1;
    float* EH0  = buf + OFF_EH0;
    float* EH1  = buf + OFF_EH1;
    float* EC0  = buf + OFF_EC0;
    float* EC1  = buf + OFF_EC1;
    float* P_DL0C = buf + OFF_PACK + 0ull*PACK_SZ;
    float* P_DL0H = buf + OFF_PACK + 1ull*PACK_SZ;
    float* P_DL1X = buf + OFF_PACK + 2ull*PACK_SZ;
    float* P_DL1H = buf + OFF_PACK + 3ull*PACK_SZ;
    float* P_EL0H = buf + OFF_PACK + 4ull*PACK_SZ;
    float* P_EL1X = buf + OFF_PACK + 5ull*PACK_SZ;
    float* P_EL1H = buf + OFF_PACK + 6ull*PACK_SZ;

    dim3 pg(4, 512);
    k_pack<<<pg, 128>>>(dec_Wih0 + H,       2*H, P_DL0C, H);
    k_pack<<<pg, 128>>>(dec_Whh,            H,   P_DL0H, H);
    k_pack<<<pg, 128>>>(dec_Wih1,           H,   P_DL1X, H);
    k_pack<<<pg, 128>>>(dec_Whh + 4*H*H,    H,   P_DL1H, H);
    k_pack<<<pg, 128>>>(enc_Whh,            H,   P_EL0H, H);
    k_pack<<<pg, 128>>>(enc_Wih + 4*H*H,    H,   P_EL1X, H);
    k_pack<<<pg, 128>>>(enc_Whh + 4*H*H,    H,   P_EL1H, H);
    k_zero<<<(ZERO_CNT + 255)/256, 256>>>();

    for (int s = 0; s < NS; s++) {
        // ---- decoder ----
        k_gather<<<T*B, 128>>>(inputs, targets, dec_emb, Xemb, s, 1);
        k_gemm<<<dim3(32, 16), 256>>>(Xemb, H, dec_Wih0, 2*H, dec_bias, G0, 4*H, H, 0, 0);
        for (int t = 0; t < T; t++) {
            int p = t & 1;
            float* h0p = DH0 + p*B*H;       float* h0n = DH0 + (p^1)*B*H;
            float* h1p = DH1 + p*B*H;       float* h1n = DH1 + (p^1)*B*H;
            if (s > 0)
                k_attn<<<B, 256>>>(h1p, Kpre, Eout, att_W, att_v, Ctx);
            k_lstm<<<128, 128>>>(G0 + (size_t)t*B*4*H, 0,
                                 Ctx, P_DL0C, H, h0p, P_DL0H, H,
                                 DC0, h0n, nullptr, 0);
            k_lstm<<<128, 128>>>(dec_bias + 4*H, 1,
                                 h0n, P_DL1X, H, h1p, P_DL1H, H,
                                 DC1, h1n, Dout + (size_t)t*B*H, H);
        }
        if (s > 0) {
            k_ln<<<T*B, 128>>>(Dout, Norm, dec_ln_g, dec_ln_b);
            k_gemm<<<dim3((V + 63)/64, 16), 256>>>(Norm, H, fc_W, H, fc_b, out, V, H, 1, s);
        }
        if (s < NS - 1) {
            k_maskk<<<1, 32>>>(inputs, targets, s);
            // ---- encoder ----
            k_gather<<<T*B, 128>>>(inputs, targets, enc_emb, Xemb, s, 0);
            k_gemm<<<dim3(32, 16), 256>>>(Xemb, H, enc_Wih, H, enc_bias, G0, 4*H, H, 0, 0);
            for (int t = 0; t < T; t++) {
                int p = t & 1;
                float* h0p = EH0 + p*B*H;   float* h0n = EH0 + (p^1)*B*H;
                float* h1p = EH1 + p*B*H;   float* h1n = EH1 + (p^1)*B*H;
                k_lstm<<<128, 128>>>(G0 + (size_t)t*B*4*H, 0,
                                     nullptr, nullptr, 0, h0p, P_EL0H, H,
                                     EC0, h0n, nullptr, 0);
                k_lstm<<<128, 128>>>(enc_bias + 4*H, 1,
                                     h0n, P_EL1X, H, h1p, P_EL1H, H,
                                     EC1, h1n, Eraw + (size_t)t*H, T*H);
            }
            k_ln<<<T*B, 128>>>(Eraw, Eout, enc_ln_g, enc_ln_b);
            k_gemm<<<dim3(8, 16), 256>>>(Eout, H, att_W + H, 2*H, att_b, Kpre, H, H, 0, 0);
        }
    }
}

// round 4
// speedup vs baseline: 2.5205x; 2.5205x over previous
#include <cuda_runtime.h>
#include <math.h>

#define H 512
#define B 32
#define T 32
#define V 6000
#define NS 6

// ---------------- scratch buffer layout (floats) ----------------
#define SZ_ROWHB (T*B*H)
#define OFF_XEMB 0
#define OFF_G0   (OFF_XEMB + SZ_ROWHB)   // [t][b][4H]
#define OFF_DOUT (OFF_G0 + T*B*4*H)      // [t][b][H]
#define OFF_NORM (OFF_DOUT + SZ_ROWHB)
#define OFF_ERAW (OFF_NORM + SZ_ROWHB)   // [b][t][H]
#define OFF_EOUT (OFF_ERAW + SZ_ROWHB)   // [b][t][H]
#define OFF_KPRE (OFF_EOUT + SZ_ROWHB)   // [b*T+t][H]
#define OFF_CTX  (OFF_KPRE + SZ_ROWHB)
#define OFF_DH0  (OFF_CTX + B*H)
#define OFF_DH1  (OFF_DH0 + 2*B*H)
#define OFF_DC0  (OFF_DH1 + 2*B*H)
#define OFF_DC1  (OFF_DC0 + B*H)
#define OFF_EH0  (OFF_DC1 + B*H)
#define OFF_EH1  (OFF_EH0 + 2*B*H)
#define OFF_EC0  (OFF_EH1 + 2*B*H)
#define OFF_EC1  (OFF_EC0 + B*H)
#define OFF_PACK (OFF_EC1 + B*H)
#define PACK_SZ  (H*H*4)
#define N_PACK   7
#define BUF_TOTAL (OFF_PACK + (size_t)N_PACK*PACK_SZ)
#define ZERO_CNT (OFF_PACK - OFF_CTX)

__device__ float g_buf[BUF_TOTAL];
__device__ int   g_mask[B*T];

typedef unsigned long long ull;

// ---------------- f32x2 helpers ----------------
#define FMA2(a,x,w) asm("fma.rn.f32x2 %0, %1, %2, %0;" : "+l"(a) : "l"(x), "l"(w))
__device__ __forceinline__ ull pk2(float lo, float hi) {
    ull r; asm("mov.b64 %0, {%1,%2};" : "=l"(r) : "f"(lo), "f"(hi)); return r;
}
__device__ __forceinline__ float2 up2(ull v) {
    float2 f; asm("mov.b64 {%0,%1}, %2;" : "=f"(f.x), "=f"(f.y) : "l"(v)); return f;
}

// ---------------- zero recurrent state ----------------
__global__ void k_zero() {
    int i = blockIdx.x * 256 + threadIdx.x;
    if (i < ZERO_CNT) g_buf[OFF_CTX + i] = 0.0f;
}

// ---------------- pack gate weights: per (j, kpair): i0,i1,f0,f1,g0,g1,o0,o1 ----------------
__global__ void k_pack2(const float* __restrict__ W, int ldw, float* __restrict__ P) {
    int kp = blockIdx.x * 128 + threadIdx.x;   // 0..255
    int j  = blockIdx.y;
    float* o = P + ((size_t)j*256 + kp)*8;
    #pragma unroll
    for (int g = 0; g < 4; g++) {
        o[g*2+0] = W[(size_t)(g*H + j) * ldw + 2*kp];
        o[g*2+1] = W[(size_t)(g*H + j) * ldw + 2*kp + 1];
    }
}

// ---------------- embedding gather ----------------
__global__ void k_gather(const int* __restrict__ inputs, const int* __restrict__ targets,
                         const float* __restrict__ emb, float* __restrict__ X,
                         int s, int is_dec) {
    int row = blockIdx.x;          // t*32 + b
    int t = row >> 5, b = row & 31;
    int tok;
    if (is_dec) {
        if (t == 0) tok = 1; // SOS
        else tok = (s == 0) ? inputs[b*192 + (t-1)] : targets[b*160 + (s-1)*32 + (t-1)];
    } else {
        tok = (s == 0) ? inputs[b*192 + t] : targets[b*160 + (s-1)*32 + t];
    }
    const float4* e = (const float4*)(emb + (size_t)tok * H);
    float4* o = (float4*)(X + (size_t)row * H);
    for (int i = threadIdx.x; i < H/4; i += 128) o[i] = e[i];
}

// ---------------- mask for next sentence ----------------
__global__ void k_maskk(const int* __restrict__ inputs, const int* __restrict__ targets, int s) {
    int b = threadIdx.x;
    if (b >= B) return;
    int seen = 0;
    for (int t = 0; t < T; t++) {
        g_mask[b*T + t] = seen;
        int tok = (s == 0) ? inputs[b*192 + t] : targets[b*160 + (s-1)*32 + t];
        if (tok == 2 || tok == 3) seen = 1;
    }
}

// ---------------- SGEMM: C[M,N] = A[M,K] @ W[N,ldw]^T + bias ----------------
__global__ void k_gemm(const float* __restrict__ A, int lda,
                       const float* __restrict__ W, int ldw,
                       const float* __restrict__ bias,
                       float* __restrict__ C, int N, int K, int mode, int s) {
    __shared__ float As[16][68];
    __shared__ float Bs[16][68];
    int tid = threadIdx.x;
    int m0 = blockIdx.y * 64, n0 = blockIdx.x * 64;
    int lr = tid >> 2, lc = (tid & 3) * 4;
    int ty = tid >> 4, tx = tid & 15;
    float acc[4][4] = {};
    for (int k0 = 0; k0 < K; k0 += 16) {
        float4 av = *(const float4*)(A + (size_t)(m0 + lr) * lda + k0 + lc);
        float4 bv = make_float4(0.f, 0.f, 0.f, 0.f);
        if (n0 + lr < N) bv = *(const float4*)(W + (size_t)(n0 + lr) * ldw + k0 + lc);
        __syncthreads();
        As[lc+0][lr] = av.x; As[lc+1][lr] = av.y; As[lc+2][lr] = av.z; As[lc+3][lr] = av.w;
        Bs[lc+0][lr] = bv.x; Bs[lc+1][lr] = bv.y; Bs[lc+2][lr] = bv.z; Bs[lc+3][lr] = bv.w;
        __syncthreads();
        #pragma unroll
        for (int k = 0; k < 16; k++) {
            float4 a = *(const float4*)&As[k][ty*4];
            float4 b = *(const float4*)&Bs[k][tx*4];
            acc[0][0] += a.x*b.x; acc[0][1] += a.x*b.y; acc[0][2] += a.x*b.z; acc[0][3] += a.x*b.w;
            acc[1][0] += a.y*b.x; acc[1][1] += a.y*b.y; acc[1][2] += a.y*b.z; acc[1][3] += a.y*b.w;
            acc[2][0] += a.z*b.x; acc[2][1] += a.z*b.y; acc[2][2] += a.z*b.z; acc[2][3] += a.z*b.w;
            acc[3][0] += a.w*b.x; acc[3][1] += a.w*b.y; acc[3][2] += a.w*b.z; acc[3][3] += a.w*b.w;
        }
    }
    #pragma unroll
    for (int i = 0; i < 4; i++)
        #pragma unroll
        for (int j = 0; j < 4; j++) {
            int m = m0 + ty*4 + i, n = n0 + tx*4 + j;
            if (n < N) {
                float v = acc[i][j] + (bias ? bias[n] : 0.f);
                if (mode == 0) C[(size_t)m * N + n] = v;
                else {
                    int t = m >> 5, b = m & 31;
                    C[(((size_t)b*5 + (s-1))*32 + t) * V + n] = v;
                }
            }
        }
}

// ---------------- cooperative stage loader for k_lstm ----------------
__device__ __forceinline__ void stage_load(
    float4 (*Ws)[4][16][2], ull (*Xs)[16][33],
    int s, int KPG, int KP1, int jb, int tid,
    const float* __restrict__ X1, const float* __restrict__ P1,
    const float* __restrict__ X2, const float* __restrict__ P2)
{
    {
        int g = tid >> 7, jjw = (tid >> 5) & 3, kp = (tid >> 1) & 15, h = tid & 1;
        int kpg = g*KPG + s*16 + kp;
        const float* Pp = (kpg < KP1) ? P1 : P2;
        int kl = (kpg < KP1) ? kpg : kpg - KP1;
        Ws[g][jjw][kp][h] = *(const float4*)(Pp + ((size_t)(jb + jjw)*256 + kl)*8 + h*4);
    }
    #pragma unroll
    for (int r = 0; r < 4; r++) {
        int idx = tid + r * 256;
        int gx = idx >> 9, bx = (idx >> 4) & 31, kx = idx & 15;
        int kpg = gx*KPG + s*16 + kx;
        const float* Xp = (kpg < KP1) ? X1 : X2;
        int kl = (kpg < KP1) ? kpg : kpg - KP1;
        Xs[gx][kx][bx] = *(const ull*)(Xp + (size_t)bx*512 + kl*2);
    }
}

// ---------------- fused LSTM step: smem-staged weights + f32x2 ----------------
__global__ __launch_bounds__(256) void k_lstm(
    const float* __restrict__ base, int base_vec,
    const float* __restrict__ X1, const float* __restrict__ P1, int K1,
    const float* __restrict__ X2, const float* __restrict__ P2, int K2,
    float* __restrict__ cst, float* __restrict__ hout,
    float* __restrict__ store, int store_bstride)
{
    __shared__ float4 Ws[2][2][4][16][2];
    __shared__ ull    Xs[2][2][16][33];
    __shared__ ull    Red[4][4][32];
    int tid = threadIdx.x, warp = tid >> 5, lane = tid & 31;
    int jj = warp & 3, grp = warp >> 2;
    int jb = blockIdx.x * 4, j = jb + jj;
    int KP1 = K1 >> 1;
    int KPG = (K1 + K2) >> 2;
    int nst = KPG >> 4;

    float cold = 0.f;
    ull ai, af, ag, ao;
    if (grp == 0) {
        cold = cst[lane*H + j];
        float bi, bf, bg, bo;
        if (base_vec) { bi = base[j]; bf = base[H+j]; bg = base[2*H+j]; bo = base[3*H+j]; }
        else {
            const float* r = base + (size_t)lane * (4*H);
            bi = r[j]; bf = r[H+j]; bg = r[2*H+j]; bo = r[3*H+j];
        }
        ai = pk2(bi, 0.f); af = pk2(bf, 0.f); ag = pk2(bg, 0.f); ao = pk2(bo, 0.f);
    } else { ai = af = ag = ao = 0ull; }

    stage_load(Ws[0], Xs[0], 0, KPG, KP1, jb, tid, X1, P1, X2, P2);
    __syncthreads();
    int buf = 0;
    for (int s = 0; s < nst; s++) {
        if (s + 1 < nst)
            stage_load(Ws[buf^1], Xs[buf^1], s+1, KPG, KP1, jb, tid, X1, P1, X2, P2);
        #pragma unroll
        for (int kp = 0; kp < 16; kp++) {
            ull x2 = Xs[buf][grp][kp][lane];
            ulonglong2 wa = *(const ulonglong2*)&Ws[buf][grp][jj][kp][0];
            ulonglong2 wb = *(const ulonglong2*)&Ws[buf][grp][jj][kp][1];
            FMA2(ai, x2, wa.x); FMA2(af, x2, wa.y);
            FMA2(ag, x2, wb.x); FMA2(ao, x2, wb.y);
        }
        __syncthreads();
        buf ^= 1;
    }
    if (grp == 1) {
        Red[jj][0][lane] = ai; Red[jj][1][lane] = af;
        Red[jj][2][lane] = ag; Red[jj][3][lane] = ao;
    }
    __syncthreads();
    if (grp == 0) {
        float2 A, R;
        A = up2(ai); R = up2(Red[jj][0][lane]); float gi = A.x + A.y + R.x + R.y;
        A = up2(af); R = up2(Red[jj][1][lane]); float gf = A.x + A.y + R.x + R.y;
        A = up2(ag); R = up2(Red[jj][2][lane]); float gg = A.x + A.y + R.x + R.y;
        A = up2(ao); R = up2(Red[jj][3][lane]); float go = A.x + A.y + R.x + R.y;
        float si = 1.f / (1.f + expf(-gi));
        float sf = 1.f / (1.f + expf(-gf));
        float so = 1.f / (1.f + expf(-go));
        float c2 = sf * cold + si * tanhf(gg);
        float h2 = so * tanhf(c2);
        cst[lane*H + j]  = c2;
        hout[lane*H + j] = h2;
        if (store) store[(size_t)lane*store_bstride + j] = h2;
    }
}

// ---------------- attention ----------------
__global__ void k_attn(const float* __restrict__ h1, const float* __restrict__ Kpre,
                       const float* __restrict__ enc_outs, const float* __restrict__ attW,
                       const float* __restrict__ attv, float* __restrict__ ctx) {
    int b = blockIdx.x, tid = threadIdx.x;
    __shared__ float h1s[H];
    __shared__ float qW[H];
    __shared__ float sc[T];
    h1s[tid]       = h1[b*H + tid];
    h1s[tid + 256] = h1[b*H + tid + 256];
    __syncthreads();
    #pragma unroll
    for (int jj = 0; jj < 2; jj++) {
        int j = tid + jj*256;
        const float4* row = (const float4*)(attW + (size_t)j * (2*H));
        const float4* hh  = (const float4*)h1s;
        float acc = 0.f;
        #pragma unroll 4
        for (int k = 0; k < H/4; k++) {
            float4 w = row[k], x = hh[k];
            acc += w.x*x.x + w.y*x.y + w.z*x.z + w.w*x.w;
        }
        qW[j] = acc;
    }
    __syncthreads();
    int warp = tid >> 5, lane = tid & 31;
    for (int t = warp; t < T; t += 8) {
        if (g_mask[b*T + t]) { if (lane == 0) sc[t] = -1e9f; continue; }
        float p = 0.f;
        const float* kp = Kpre + ((size_t)b*T + t) * H;
        for (int j = lane; j < H; j += 32) p += tanhf(qW[j] + kp[j]) * attv[j];
        for (int o = 16; o; o >>= 1) p += __shfl_xor_sync(0xffffffffu, p, o);
        if (lane == 0) sc[t] = p;
    }
    __syncthreads();
    if (tid < 32) {
        float v = sc[tid];
        float m = v;
        for (int o = 16; o; o >>= 1) m = fmaxf(m, __shfl_xor_sync(0xffffffffu, m, o));
        float e = expf(v - m);
        float ssum = e;
        for (int o = 16; o; o >>= 1) ssum += __shfl_xor_sync(0xffffffffu, ssum, o);
        sc[tid] = e / ssum;
    }
    __syncthreads();
    #pragma unroll
    for (int jj = 0; jj < 2; jj++) {
        int hc = tid + jj*256;
        float acc = 0.f;
        const float* eo = enc_outs + (size_t)b*T*H + hc;
        #pragma unroll
        for (int t = 0; t < T; t++) acc += sc[t] * eo[(size_t)t*H];
        ctx[b*H + hc] = acc;
    }
}

// ---------------- layernorm ----------------
__global__ void k_ln(const float* __restrict__ in, float* __restrict__ out,
                     const float* __restrict__ g, const float* __restrict__ bb) {
    int row = blockIdx.x, tid = threadIdx.x;
    const float* x = in + (size_t)row * H;
    float v[4], s = 0.f;
    #pragma unroll
    for (int i = 0; i < 4; i++) { v[i] = x[tid + i*128]; s += v[i]; }
    __shared__ float rs[4];
    for (int o = 16; o; o >>= 1) s += __shfl_xor_sync(0xffffffffu, s, o);
    int warp = tid >> 5, lane = tid & 31;
    if (lane == 0) rs[warp] = s;
    __syncthreads();
    float mean = (rs[0] + rs[1] + rs[2] + rs[3]) / (float)H;
    __syncthreads();
    float s2 = 0.f;
    #pragma unroll
    for (int i = 0; i < 4; i++) { float d = v[i] - mean; s2 += d*d; }
    for (int o = 16; o; o >>= 1) s2 += __shfl_xor_sync(0xffffffffu, s2, o);
    if (lane == 0) rs[warp] = s2;
    __syncthreads();
    float var = (rs[0] + rs[1] + rs[2] + rs[3]) / (float)H;
    float inv = rsqrtf(var + 1e-5f);
    #pragma unroll
    for (int i = 0; i < 4; i++) {
        int c = tid + i*128;
        out[(size_t)row*H + c] = (v[i] - mean) * inv * g[c] + bb[c];
    }
}

// ---------------- host orchestration ----------------
extern "C" void kernel_launch(void* const* d_in, const int* in_sizes, int n_in,
                              void* d_out, int out_size) {
    const int*   inputs   = (const int*)d_in[0];
    const int*   targets  = (const int*)d_in[1];
    const float* enc_emb  = (const float*)d_in[2];
    const float* enc_Wih  = (const float*)d_in[3];
    const float* enc_Whh  = (const float*)d_in[4];
    const float* enc_bias = (const float*)d_in[5];
    const float* enc_ln_g = (const float*)d_in[6];
    const float* enc_ln_b = (const float*)d_in[7];
    const float* dec_emb  = (const float*)d_in[8];
    const float* att_W    = (const float*)d_in[9];
    const float* att_b    = (const float*)d_in[10];
    const float* att_v    = (const float*)d_in[11];
    const float* dec_Wih0 = (const float*)d_in[12];
    const float* dec_Wih1 = (const float*)d_in[13];
    const float* dec_Whh  = (const float*)d_in[14];
    const float* dec_bias = (const float*)d_in[15];
    const float* dec_ln_g = (const float*)d_in[16];
    const float* dec_ln_b = (const float*)d_in[17];
    const float* fc_W     = (const float*)d_in[18];
    const float* fc_b     = (const float*)d_in[19];
    float* out = (float*)d_out;

    float* buf = nullptr;
    cudaGetSymbolAddress((void**)&buf, g_buf);

    float* Xemb = buf + OFF_XEMB;
    float* G0   = buf + OFF_G0;
    float* Dout = buf + OFF_DOUT;
    float* Norm = buf + OFF_NORM;
    float* Eraw = buf + OFF_ERAW;
    float* Eout = buf + OFF_EOUT;
    float* Kpre = buf + OFF_KPRE;
    float* Ctx  = buf + OFF_CTX;
    float* DH0  = buf + OFF_DH0;
    float* DH1  = buf + OFF_DH1;
    float* DC0  = buf + OFF_DC0;
    float* DC1  = buf + OFF_DC1;
    float* EH0  = buf + OFF_EH0;
    float* EH1  = buf + OFF_EH1;
    float* EC0  = buf + OFF_EC0;
    float* EC1  = buf + OFF_EC1;
    float* P_DL0C = buf + OFF_PACK + 0ull*PACK_SZ;
    float* P_DL0H = buf + OFF_PACK + 1ull*PACK_SZ;
    float* P_DL1X = buf + OFF_PACK + 2ull*PACK_SZ;
    float* P_DL1H = buf + OFF_PACK + 3ull*PACK_SZ;
    float* P_EL0H = buf + OFF_PACK + 4ull*PACK_SZ;
    float* P_EL1X = buf + OFF_PACK + 5ull*PACK_SZ;
    float* P_EL1H = buf + OFF_PACK + 6ull*PACK_SZ;

    dim3 pg(2, 512);
    k_pack2<<<pg, 128>>>(dec_Wih0 + H,       2*H, P_DL0C);
    k_pack2<<<pg, 128>>>(dec_Whh,            H,   P_DL0H);
    k_pack2<<<pg, 128>>>(dec_Wih1,           H,   P_DL1X);
    k_pack2<<<pg, 128>>>(dec_Whh + 4*H*H,    H,   P_DL1H);
    k_pack2<<<pg, 128>>>(enc_Whh,            H,   P_EL0H);
    k_pack2<<<pg, 128>>>(enc_Wih + 4*H*H,    H,   P_EL1X);
    k_pack2<<<pg, 128>>>(enc_Whh + 4*H*H,    H,   P_EL1H);
    k_zero<<<(ZERO_CNT + 255)/256, 256>>>();

    for (int s = 0; s < NS; s++) {
        // ---- decoder ----
        k_gather<<<T*B, 128>>>(inputs, targets, dec_emb, Xemb, s, 1);
        k_gemm<<<dim3(32, 16), 256>>>(Xemb, H, dec_Wih0, 2*H, dec_bias, G0, 4*H, H, 0, 0);
        for (int t = 0; t < T; t++) {
            int p = t & 1;
            float* h0p = DH0 + p*B*H;       float* h0n = DH0 + (p^1)*B*H;
            float* h1p = DH1 + p*B*H;       float* h1n = DH1 + (p^1)*B*H;
            if (s > 0)
                k_attn<<<B, 256>>>(h1p, Kpre, Eout, att_W, att_v, Ctx);
            k_lstm<<<128, 256>>>(G0 + (size_t)t*B*4*H, 0,
                                 Ctx, P_DL0C, H, h0p, P_DL0H, H,
                                 DC0, h0n, nullptr, 0);
            k_lstm<<<128, 256>>>(dec_bias + 4*H, 1,
                                 h0n, P_DL1X, H, h1p, P_DL1H, H,
                                 DC1, h1n, Dout + (size_t)t*B*H, H);
        }
        if (s > 0) {
            k_ln<<<T*B, 128>>>(Dout, Norm, dec_ln_g, dec_ln_b);
            k_gemm<<<dim3((V + 63)/64, 16), 256>>>(Norm, H, fc_W, H, fc_b, out, V, H, 1, s);
        }
        if (s < NS - 1) {
            k_maskk<<<1, 32>>>(inputs, targets, s);
            // ---- encoder ----
            k_gather<<<T*B, 128>>>(inputs, targets, enc_emb, Xemb, s, 0);
            k_gemm<<<dim3(32, 16), 256>>>(Xemb, H, enc_Wih, H, enc_bias, G0, 4*H, H, 0, 0);
            for (int t = 0; t < T; t++) {
                int p = t & 1;
                float* h0p = EH0 + p*B*H;   float* h0n = EH0 + (p^1)*B*H;
                float* h1p = EH1 + p*B*H;   float* h1n = EH1 + (p^1)*B*H;
                k_lstm<<<128, 256>>>(G0 + (size_t)t*B*4*H, 0,
                                     nullptr, nullptr, 0, h0p, P_EL0H, H,
                                     EC0, h0n, nullptr, 0);
                k_lstm<<<128, 256>>>(enc_bias + 4*H, 1,
                                     h0n, P_EL1X, H, h1p, P_EL1H, H,
                                     EC1, h1n, Eraw + (size_t)t*H, T*H);
            }
            k_ln<<<T*B, 128>>>(Eraw, Eout, enc_ln_g, enc_ln_b);
            k_gemm<<<dim3(8, 16), 256>>>(Eout, H, att_W + H, 2*H, att_b, Kpre, H, H, 0, 0);
        }
    }
}

// round 6
// speedup vs baseline: 5.7880x; 2.2964x over previous
#include <cuda_runtime.h>
#include <math.h>

#define H 512
#define B 32
#define T 32
#define V 6000
#define NS 6
#define HB (H*B)                 // 16384 floats per state vector set
#define NBLK 128

typedef unsigned long long ull;

// ---------------- scratch layout (floats) ----------------
// Pair-transposed (PT) layout for recurrent vectors: float (b,k) at (k>>1)*64 + b*2 + (k&1)
#define OFF_CTXT 0
#define OFF_QT   (OFF_CTXT + HB)
#define OFF_DH0T (OFF_QT + HB)          // 2 buffers
#define OFF_DH1T (OFF_DH0T + 2*HB)      // 2 buffers
#define OFF_EH0T (OFF_DH1T + 2*HB)
#define OFF_EH1T (OFF_EH0T + 2*HB)
#define OFF_DC0  (OFF_EH1T + 2*HB)      // natural [b][H]
#define OFF_DC1  (OFF_DC0 + HB)
#define OFF_EC0  (OFF_DC1 + HB)
#define OFF_EC1  (OFF_EC0 + HB)
#define ZERO_CNT (OFF_EC1 + HB)
#define OFF_XEMB ZERO_CNT
#define OFF_G0   (OFF_XEMB + T*B*H)     // [t][b][4H]
#define OFF_DOUT (OFF_G0 + T*B*4*H)     // [t][b][H]
#define OFF_NORM (OFF_DOUT + T*B*H)
#define OFF_ERAW (OFF_NORM + T*B*H)     // [b][t][H]
#define OFF_EOUT (OFF_ERAW + T*B*H)
#define OFF_KPRE (OFF_EOUT + T*B*H)     // [b*T+t][H]
#define OFF_PACK (OFF_KPRE + T*B*H)
#define PACK_SZ  (H*H*4)
#define N_PACK   7
#define BUF_TOTAL (OFF_PACK + (size_t)N_PACK*PACK_SZ)

__device__ float g_buf[BUF_TOTAL];
__device__ int   g_mask[B*T];
__device__ unsigned g_gen;
__device__ unsigned g_arr[NBLK];

// ---------------- low-level helpers ----------------
#define FMA2(a,x,w) asm("fma.rn.f32x2 %0, %1, %2, %0;" : "+l"(a) : "l"(x), "l"(w))
__device__ __forceinline__ ull pk2(float lo, float hi) {
    ull r; asm("mov.b64 %0, {%1,%2};" : "=l"(r) : "f"(lo), "f"(hi)); return r;
}
__device__ __forceinline__ float2 up2(ull v) {
    float2 f; asm("mov.b64 {%0,%1}, %2;" : "=f"(f.x), "=f"(f.y) : "l"(v)); return f;
}
__device__ __forceinline__ ull ldcg64(const ull* p) {
    ull v; asm volatile("ld.global.cg.b64 %0, [%1];" : "=l"(v) : "l"(p)); return v;
}
__device__ __forceinline__ float ldcgf(const float* p) {
    float v; asm volatile("ld.global.cg.f32 %0, [%1];" : "=f"(v) : "l"(p)); return v;
}
__device__ __forceinline__ void st_rel(unsigned* p, unsigned v) {
    asm volatile("st.release.gpu.global.u32 [%0], %1;" :: "l"(p), "r"(v) : "memory");
}
__device__ __forceinline__ unsigned ld_acq(const unsigned* p) {
    unsigned v; asm volatile("ld.acquire.gpu.global.u32 %0, [%1];" : "=r"(v) : "l"(p) : "memory"); return v;
}

// ---------------- grid barrier (monotonic generations; replay-safe) ----------------
__device__ __forceinline__ void gridbar(unsigned &mygen) {
    __syncthreads();
    mygen++;
    if (threadIdx.x == 0) st_rel(&g_arr[blockIdx.x], mygen);
    if (blockIdx.x == 0) {
        if (threadIdx.x < NBLK) {
            while ((int)(ld_acq(&g_arr[threadIdx.x]) - mygen) < 0) { }
        }
        __syncthreads();
        if (threadIdx.x == 0) st_rel(&g_gen, mygen);
    } else {
        if (threadIdx.x == 0) {
            while ((int)(ld_acq(&g_gen) - mygen) < 0) { }
        }
        __syncthreads();
    }
}

// ---------------- zero recurrent state ----------------
__global__ void k_zero() {
    int i = blockIdx.x * 256 + threadIdx.x;
    if (i < ZERO_CNT) g_buf[i] = 0.0f;
}

// ---------------- pack gate weights: per (j, kpair): i0,i1,f0,f1,g0,g1,o0,o1 ----------------
__global__ void k_pack2(const float* __restrict__ W, int ldw, float* __restrict__ P) {
    int kp = blockIdx.x * 128 + threadIdx.x;   // 0..255
    int j  = blockIdx.y;
    float* o = P + ((size_t)j*256 + kp)*8;
    #pragma unroll
    for (int g = 0; g < 4; g++) {
        o[g*2+0] = W[(size_t)(g*H + j) * ldw + 2*kp];
        o[g*2+1] = W[(size_t)(g*H + j) * ldw + 2*kp + 1];
    }
}

// ---------------- embedding gather ----------------
__global__ void k_gather(const int* __restrict__ inputs, const int* __restrict__ targets,
                         const float* __restrict__ emb, float* __restrict__ X,
                         int s, int is_dec) {
    int row = blockIdx.x;          // t*32 + b
    int t = row >> 5, b = row & 31;
    int tok;
    if (is_dec) {
        if (t == 0) tok = 1; // SOS
        else tok = (s == 0) ? inputs[b*192 + (t-1)] : targets[b*160 + (s-1)*32 + (t-1)];
    } else {
        tok = (s == 0) ? inputs[b*192 + t] : targets[b*160 + (s-1)*32 + t];
    }
    const float4* e = (const float4*)(emb + (size_t)tok * H);
    float4* o = (float4*)(X + (size_t)row * H);
    for (int i = threadIdx.x; i < H/4; i += 128) o[i] = e[i];
}

// ---------------- mask for next sentence ----------------
__global__ void k_maskk(const int* __restrict__ inputs, const int* __restrict__ targets, int s) {
    int b = threadIdx.x;
    if (b >= B) return;
    int seen = 0;
    for (int t = 0; t < T; t++) {
        g_mask[b*T + t] = seen;
        int tok = (s == 0) ? inputs[b*192 + t] : targets[b*160 + (s-1)*32 + t];
        if (tok == 2 || tok == 3) seen = 1;
    }
}

// ---------------- SGEMM: C[M,N] = A[M,K] @ W[N,ldw]^T + bias ----------------
__global__ void k_gemm(const float* __restrict__ A, int lda,
                       const float* __restrict__ W, int ldw,
                       const float* __restrict__ bias,
                       float* __restrict__ C, int N, int K, int mode, int s) {
    __shared__ float As[16][68];
    __shared__ float Bs[16][68];
    int tid = threadIdx.x;
    int m0 = blockIdx.y * 64, n0 = blockIdx.x * 64;
    int lr = tid >> 2, lc = (tid & 3) * 4;
    int ty = tid >> 4, tx = tid & 15;
    float acc[4][4] = {};
    for (int k0 = 0; k0 < K; k0 += 16) {
        float4 av = *(const float4*)(A + (size_t)(m0 + lr) * lda + k0 + lc);
        float4 bv = make_float4(0.f, 0.f, 0.f, 0.f);
        if (n0 + lr < N) bv = *(const float4*)(W + (size_t)(n0 + lr) * ldw + k0 + lc);
        __syncthreads();
        As[lc+0][lr] = av.x; As[lc+1][lr] = av.y; As[lc+2][lr] = av.z; As[lc+3][lr] = av.w;
        Bs[lc+0][lr] = bv.x; Bs[lc+1][lr] = bv.y; Bs[lc+2][lr] = bv.z; Bs[lc+3][lr] = bv.w;
        __syncthreads();
        #pragma unroll
        for (int k = 0; k < 16; k++) {
            float4 a = *(const float4*)&As[k][ty*4];
            float4 b = *(const float4*)&Bs[k][tx*4];
            acc[0][0] += a.x*b.x; acc[0][1] += a.x*b.y; acc[0][2] += a.x*b.z; acc[0][3] += a.x*b.w;
            acc[1][0] += a.y*b.x; acc[1][1] += a.y*b.y; acc[1][2] += a.y*b.z; acc[1][3] += a.y*b.w;
            acc[2][0] += a.z*b.x; acc[2][1] += a.z*b.y; acc[2][2] += a.z*b.z; acc[2][3] += a.z*b.w;
            acc[3][0] += a.w*b.x; acc[3][1] += a.w*b.y; acc[3][2] += a.w*b.z; acc[3][3] += a.w*b.w;
        }
    }
    #pragma unroll
    for (int i = 0; i < 4; i++)
        #pragma unroll
        for (int j = 0; j < 4; j++) {
            int m = m0 + ty*4 + i, n = n0 + tx*4 + j;
            if (n < N) {
                float v = acc[i][j] + (bias ? bias[n] : 0.f);
                if (mode == 0) C[(size_t)m * N + n] = v;
                else {
                    int t = m >> 5, b = m & 31;
                    C[(((size_t)b*5 + (s-1))*32 + t) * V + n] = v;
                }
            }
        }
}

// ---------------- layernorm ----------------
__global__ void k_ln(const float* __restrict__ in, float* __restrict__ out,
                     const float* __restrict__ g, const float* __restrict__ bb) {
    int row = blockIdx.x, tid = threadIdx.x;
    const float* x = in + (size_t)row * H;
    float v[4], s = 0.f;
    #pragma unroll
    for (int i = 0; i < 4; i++) { v[i] = x[tid + i*128]; s += v[i]; }
    __shared__ float rs[4];
    for (int o = 16; o; o >>= 1) s += __shfl_xor_sync(0xffffffffu, s, o);
    int warp = tid >> 5, lane = tid & 31;
    if (lane == 0) rs[warp] = s;
    __syncthreads();
    float mean = (rs[0] + rs[1] + rs[2] + rs[3]) / (float)H;
    __syncthreads();
    float s2 = 0.f;
    #pragma unroll
    for (int i = 0; i < 4; i++) { float d = v[i] - mean; s2 += d*d; }
    for (int o = 16; o; o >>= 1) s2 += __shfl_xor_sync(0xffffffffu, s2, o);
    if (lane == 0) rs[warp] = s2;
    __syncthreads();
    float var = (rs[0] + rs[1] + rs[2] + rs[3]) / (float)H;
    float inv = rsqrtf(var + 1e-5f);
    #pragma unroll
    for (int i = 0; i < 4; i++) {
        int c = tid + i*128;
        out[(size_t)row*H + c] = (v[i] - mean) * inv * g[c] + bb[c];
    }
}

// ---------------- LSTM phase (inside persistent kernels) ----------------
// warp: jj = warp&3 (unit within block), grp = warp>>2 (K-half).
// wv: smem weight base for this warp (nkp*2 ulonglong2 entries).
// xsrc: PT activation source for this grp; xkp0: starting kp within it.
__device__ __forceinline__ void lstm_phase(
    const ulonglong2* wv, int nkp, int xkp0,
    const float* base, int base_vec,
    const float* xsrc,
    ull (*Red)[4][32],
    int jj, int grp, int lane, int j,
    float* cst, float* hT,
    float* extraBase, int extraStride)
{
    ull ai, af, ag, ao;
    float cold = 0.f;
    if (grp == 0) {
        cold = ldcgf(cst + (size_t)lane*H + j);
        float bi, bf, bg, bo;
        if (base_vec) { bi = base[j]; bf = base[H+j]; bg = base[2*H+j]; bo = base[3*H+j]; }
        else {
            const float* r = base + (size_t)lane * (4*H);
            bi = r[j]; bf = r[H+j]; bg = r[2*H+j]; bo = r[3*H+j];
        }
        ai = pk2(bi, 0.f); af = pk2(bf, 0.f); ag = pk2(bg, 0.f); ao = pk2(bo, 0.f);
    } else { ai = af = ag = ao = 0ull; }

    const ull* xu = (const ull*)xsrc + (size_t)xkp0*32 + lane;
    #pragma unroll 8
    for (int kp = 0; kp < nkp; kp++) {
        ull x2 = ldcg64(xu + (size_t)kp*32);
        ulonglong2 wa = wv[kp*2];
        ulonglong2 wb = wv[kp*2 + 1];
        FMA2(ai, x2, wa.x); FMA2(af, x2, wa.y);
        FMA2(ag, x2, wb.x); FMA2(ao, x2, wb.y);
    }
    if (grp == 1) {
        Red[jj][0][lane] = ai; Red[jj][1][lane] = af;
        Red[jj][2][lane] = ag; Red[jj][3][lane] = ao;
    }
    __syncthreads();
    if (grp == 0) {
        float2 A, R;
        A = up2(ai); R = up2(Red[jj][0][lane]); float gi = A.x + A.y + R.x + R.y;
        A = up2(af); R = up2(Red[jj][1][lane]); float gf = A.x + A.y + R.x + R.y;
        A = up2(ag); R = up2(Red[jj][2][lane]); float gg = A.x + A.y + R.x + R.y;
        A = up2(ao); R = up2(Red[jj][3][lane]); float go = A.x + A.y + R.x + R.y;
        float si = 1.f / (1.f + expf(-gi));
        float sf = 1.f / (1.f + expf(-gf));
        float so = 1.f / (1.f + expf(-go));
        float c2 = sf * cold + si * tanhf(gg);
        float h2 = so * tanhf(c2);
        cst[(size_t)lane*H + j] = c2;
        hT[((j>>1)*64) + lane*2 + (j&1)] = h2;
        if (extraBase) extraBase[(size_t)lane*extraStride + j] = h2;
    }
}

// ---------------- persistent decoder kernel (one sentence, grid=128) ----------------
#define SMEM_DEC (131072 + 4096 + 2048 + 256)
__global__ __launch_bounds__(256, 1) void k_dec(
    const float* __restrict__ G0, const float* __restrict__ biasL1,
    const float* __restrict__ PC, const float* __restrict__ PH0,
    const float* __restrict__ PX1, const float* __restrict__ PH1,
    float* ctxT, float* h0T, float* h1T, float* c0, float* c1,
    float* qT, const float* __restrict__ attW, const float* __restrict__ attv,
    const float* __restrict__ Kpre, const float* __restrict__ Eout,
    float* Dout, int has_attn)
{
    extern __shared__ char smem[];
    float4* Wsm = (float4*)smem;
    ull (*Red)[4][32] = (ull (*)[4][32])(smem + 131072);
    float* qs = (float*)(smem + 131072 + 4096);
    float* sc = (float*)(smem + 131072 + 4096 + 2048);

    int tid = threadIdx.x, warp = tid >> 5, lane = tid & 31;
    int jj = warp & 3, grp = warp >> 2;
    int bid = blockIdx.x;
    int j = bid*4 + jj;
    unsigned mygen = ld_acq(&g_gen);

    // load weights: 16 segments of 512 float4 (layer, jj, grp-source)
    const float* srcs[4] = { PC, PH0, PX1, PH1 };
    for (int seg = 0; seg < 16; seg++) {
        int layer = seg >> 3, sjj = (seg >> 1) & 3, sgrp = seg & 1;
        const float4* s4 = (const float4*)srcs[layer*2 + sgrp] + (size_t)(4*bid + sjj)*512;
        float4* d4 = Wsm + ((size_t)((layer*4 + sjj)*2 + sgrp))*512;
        for (int i = tid; i < 512; i += 256) d4[i] = s4[i];
    }
    __syncthreads();

    const ulonglong2* wv0 = (const ulonglong2*)(Wsm + ((size_t)((0*4 + jj)*2 + grp))*512);
    const ulonglong2* wv1 = (const ulonglong2*)(Wsm + ((size_t)((1*4 + jj)*2 + grp))*512);

    for (int t = 0; t < T; t++) {
        int p = t & 1;
        float* h0r = h0T + p*HB;  float* h0w = h0T + (p^1)*HB;
        float* h1r = h1T + p*HB;  float* h1w = h1T + (p^1)*HB;

        if (has_attn) {
            // ---- Q phase: q[b][j] = attW_q[j] · h1_prev[b], all 128 blocks ----
            {
                ull aq = 0ull;
                const ull* wrow = (const ull*)(attW + (size_t)j * 1024);
                const ull* xu = (const ull*)h1r + lane;
                int kp0 = grp * 128;
                #pragma unroll 8
                for (int kk = 0; kk < 128; kk++) {
                    ull x2 = ldcg64(xu + (size_t)(kp0 + kk)*32);
                    FMA2(aq, x2, wrow[kp0 + kk]);
                }
                if (grp == 1) Red[jj][0][lane] = aq;
                __syncthreads();
                if (grp == 0) {
                    float2 A = up2(aq), R = up2(Red[jj][0][lane]);
                    qT[((j>>1)*64) + lane*2 + (j&1)] = A.x + A.y + R.x + R.y;
                }
            }
            gridbar(mygen);
            // ---- ATTN phase: blocks 0..31, b = bid ----
            if (bid < 32) {
                const int b = bid;
                const ull* qu = (const ull*)qT + b;
                for (int i = tid; i < 256; i += 256) ((ull*)qs)[i] = ldcg64(qu + (size_t)i*32);
                __syncthreads();
                for (int tt = warp; tt < T; tt += 8) {
                    if (g_mask[b*T + tt]) { if (lane == 0) sc[tt] = -1e9f; }
                    else {
                        float acc = 0.f;
                        const float* kr = Kpre + ((size_t)b*T + tt)*H;
                        #pragma unroll 4
                        for (int j2 = lane; j2 < H; j2 += 32) acc += tanhf(qs[j2] + kr[j2]) * attv[j2];
                        for (int o = 16; o; o >>= 1) acc += __shfl_xor_sync(0xffffffffu, acc, o);
                        if (lane == 0) sc[tt] = acc;
                    }
                }
                __syncthreads();
                if (tid < 32) {
                    float v = sc[tid], m = v;
                    for (int o = 16; o; o >>= 1) m = fmaxf(m, __shfl_xor_sync(0xffffffffu, m, o));
                    float e = expf(v - m), ss = e;
                    for (int o = 16; o; o >>= 1) ss += __shfl_xor_sync(0xffffffffu, ss, o);
                    sc[tid] = e / ss;
                }
                __syncthreads();
                #pragma unroll
                for (int h2 = 0; h2 < 2; h2++) {
                    int j2 = tid + h2*256;
                    float acc = 0.f;
                    const float* eo = Eout + (size_t)b*T*H + j2;
                    #pragma unroll
                    for (int t2 = 0; t2 < T; t2++) acc += sc[t2] * eo[(size_t)t2*H];
                    ctxT[((j2>>1)*64) + b*2 + (j2&1)] = acc;
                }
            }
            gridbar(mygen);
        }
        // ---- L0 ----
        lstm_phase(wv0, 256, 0, G0 + (size_t)t*B*4*H, 0,
                   grp ? h0r : ctxT, Red, jj, grp, lane, j,
                   c0, h0w, (float*)0, 0);
        gridbar(mygen);
        // ---- L1 ----
        lstm_phase(wv1, 256, 0, biasL1, 1,
                   grp ? h1r : h0w, Red, jj, grp, lane, j,
                   c1, h1w, Dout + (size_t)t*B*H, H);
        gridbar(mygen);
    }
}

// ---------------- persistent encoder kernel (one sentence, grid=128) ----------------
#define SMEM_ENC (98304 + 4096)
__global__ __launch_bounds__(256, 1) void k_enc(
    const float* __restrict__ G0, const float* __restrict__ biasL1,
    const float* __restrict__ PH0, const float* __restrict__ PX1, const float* __restrict__ PH1,
    float* h0T, float* h1T, float* c0, float* c1, float* Eraw)
{
    extern __shared__ char smem[];
    float4* Wsm = (float4*)smem;
    ull (*Red)[4][32] = (ull (*)[4][32])(smem + 98304);

    int tid = threadIdx.x, warp = tid >> 5, lane = tid & 31;
    int jj = warp & 3, grp = warp >> 2;
    int bid = blockIdx.x;
    int j = bid*4 + jj;
    unsigned mygen = ld_acq(&g_gen);

    // L0 weights: 8 segments of 256 f4 (jj, grp splits the 256-kp source)
    for (int seg = 0; seg < 8; seg++) {
        int sjj = seg >> 1, sgrp = seg & 1;
        const float4* s4 = (const float4*)PH0 + (size_t)(4*bid + sjj)*512 + sgrp*256;
        float4* d4 = Wsm + (size_t)(sjj*2 + sgrp)*256;
        for (int i = tid; i < 256; i += 256) d4[i] = s4[i];
    }
    // L1 weights: 8 segments of 512 f4
    for (int seg = 0; seg < 8; seg++) {
        int sjj = seg >> 1, sgrp = seg & 1;
        const float4* s4 = (const float4*)(sgrp ? PH1 : PX1) + (size_t)(4*bid + sjj)*512;
        float4* d4 = Wsm + 2048 + (size_t)(sjj*2 + sgrp)*512;
        for (int i = tid; i < 512; i += 256) d4[i] = s4[i];
    }
    __syncthreads();

    const ulonglong2* wv0 = (const ulonglong2*)(Wsm + (size_t)(jj*2 + grp)*256);
    const ulonglong2* wv1 = (const ulonglong2*)(Wsm + 2048 + (size_t)(jj*2 + grp)*512);

    for (int t = 0; t < T; t++) {
        int p = t & 1;
        float* h0r = h0T + p*HB;  float* h0w = h0T + (p^1)*HB;
        float* h1r = h1T + p*HB;  float* h1w = h1T + (p^1)*HB;
        // ---- L0: single 256-kp source (h0), grp splits kp range ----
        lstm_phase(wv0, 128, grp*128, G0 + (size_t)t*B*4*H, 0,
                   h0r, Red, jj, grp, lane, j, c0, h0w, (float*)0, 0);
        gridbar(mygen);
        // ---- L1 ----
        lstm_phase(wv1, 256, 0, biasL1, 1,
                   grp ? h1r : h0w, Red, jj, grp, lane, j,
                   c1, h1w, Eraw + (size_t)t*H, T*H);
        gridbar(mygen);
    }
}

// ---------------- host orchestration ----------------
extern "C" void kernel_launch(void* const* d_in, const int* in_sizes, int n_in,
                              void* d_out, int out_size) {
    const int*   inputs   = (const int*)d_in[0];
    const int*   targets  = (const int*)d_in[1];
    const float* enc_emb  = (const float*)d_in[2];
    const float* enc_Wih  = (const float*)d_in[3];
    const float* enc_Whh  = (const float*)d_in[4];
    const float* enc_bias = (const float*)d_in[5];
    const float* enc_ln_g = (const float*)d_in[6];
    const float* enc_ln_b = (const float*)d_in[7];
    const float* dec_emb  = (const float*)d_in[8];
    const float* att_W    = (const float*)d_in[9];
    const float* att_b    = (const float*)d_in[10];
    const float* att_v    = (const float*)d_in[11];
    const float* dec_Wih0 = (const float*)d_in[12];
    const float* dec_Wih1 = (const float*)d_in[13];
    const float* dec_Whh  = (const float*)d_in[14];
    const float* dec_bias = (const float*)d_in[15];
    const float* dec_ln_g = (const float*)d_in[16];
    const float* dec_ln_b = (const float*)d_in[17];
    const float* fc_W     = (const float*)d_in[18];
    const float* fc_b     = (const float*)d_in[19];
    float* out = (float*)d_out;

    float* buf = nullptr;
    cudaGetSymbolAddress((void**)&buf, g_buf);

    float* CtxT = buf + OFF_CTXT;
    float* QT   = buf + OFF_QT;
    float* DH0T = buf + OFF_DH0T;
    float* DH1T = buf + OFF_DH1T;
    float* EH0T = buf + OFF_EH0T;
    float* EH1T = buf + OFF_EH1T;
    float* DC0  = buf + OFF_DC0;
    float* DC1  = buf + OFF_DC1;
    float* EC0  = buf + OFF_EC0;
    float* EC1  = buf + OFF_EC1;
    float* Xemb = buf + OFF_XEMB;
    float* G0   = buf + OFF_G0;
    float* Dout = buf + OFF_DOUT;
    float* Norm = buf + OFF_NORM;
    float* Eraw = buf + OFF_ERAW;
    float* Eout = buf + OFF_EOUT;
    float* Kpre = buf + OFF_KPRE;
    float* P_DL0C = buf + OFF_PACK + 0ull*PACK_SZ;
    float* P_DL0H = buf + OFF_PACK + 1ull*PACK_SZ;
    float* P_DL1X = buf + OFF_PACK + 2ull*PACK_SZ;
    float* P_DL1H = buf + OFF_PACK + 3ull*PACK_SZ;
    float* P_EL0H = buf + OFF_PACK + 4ull*PACK_SZ;
    float* P_EL1X = buf + OFF_PACK + 5ull*PACK_SZ;
    float* P_EL1H = buf + OFF_PACK + 6ull*PACK_SZ;

    cudaFuncSetAttribute(k_dec, cudaFuncAttributeMaxDynamicSharedMemorySize, SMEM_DEC);
    cudaFuncSetAttribute(k_enc, cudaFuncAttributeMaxDynamicSharedMemorySize, SMEM_ENC);

    dim3 pg(2, 512);
    k_pack2<<<pg, 128>>>(dec_Wih0 + H,       2*H, P_DL0C);
    k_pack2<<<pg, 128>>>(dec_Whh,            H,   P_DL0H);
    k_pack2<<<pg, 128>>>(dec_Wih1,           H,   P_DL1X);
    k_pack2<<<pg, 128>>>(dec_Whh + 4*H*H,    H,   P_DL1H);
    k_pack2<<<pg, 128>>>(enc_Whh,            H,   P_EL0H);
    k_pack2<<<pg, 128>>>(enc_Wih + 4*H*H,    H,   P_EL1X);
    k_pack2<<<pg, 128>>>(enc_Whh + 4*H*H,    H,   P_EL1H);
    k_zero<<<(ZERO_CNT + 255)/256, 256>>>();

    for (int s = 0; s < NS; s++) {
        // ---- decoder ----
        k_gather<<<T*B, 128>>>(inputs, targets, dec_emb, Xemb, s, 1);
        k_gemm<<<dim3(32, 16), 256>>>(Xemb, H, dec_Wih0, 2*H, dec_bias, G0, 4*H, H, 0, 0);
        k_dec<<<NBLK, 256, SMEM_DEC>>>(G0, dec_bias + 4*H,
                                       P_DL0C, P_DL0H, P_DL1X, P_DL1H,
                                       CtxT, DH0T, DH1T, DC0, DC1,
                                       QT, att_W, att_v, Kpre, Eout, Dout,
                                       (s > 0) ? 1 : 0);
        if (s > 0) {
            k_ln<<<T*B, 128>>>(Dout, Norm, dec_ln_g, dec_ln_b);
            k_gemm<<<dim3((V + 63)/64, 16), 256>>>(Norm, H, fc_W, H, fc_b, out, V, H, 1, s);
        }
        if (s < NS - 1) {
            k_maskk<<<1, 32>>>(inputs, targets, s);
            // ---- encoder ----
            k_gather<<<T*B, 128>>>(inputs, targets, enc_emb, Xemb, s, 0);
            k_gemm<<<dim3(32, 16), 256>>>(Xemb, H, enc_Wih, H, enc_bias, G0, 4*H, H, 0, 0);
            k_enc<<<NBLK, 256, SMEM_ENC>>>(G0, enc_bias + 4*H,
                                           P_EL0H, P_EL1X, P_EL1H,
                                           EH0T, EH1T, EC0, EC1, Eraw);
            k_ln<<<T*B, 128>>>(Eraw, Eout, enc_ln_g, enc_ln_b);
            k_gemm<<<dim3(8, 16), 256>>>(Eout, H, att_W + H, 2*H, att_b, Kpre, H, H, 0, 0);
        }
    }
}

// round 7
// speedup vs baseline: 6.8026x; 1.1753x over previous
#include <cuda_runtime.h>
#include <math.h>

#define H 512
#define B 32
#define T 32
#define V 6000
#define NS 6
#define HB (H*B)
#define NBLK 128

typedef unsigned long long ull;

// ---------------- scratch layout (floats) ----------------
// Pair-transposed (PT) layout: float (b,k) at (k>>1)*64 + b*2 + (k&1)
#define OFF_CTXT 0
#define OFF_QT   (OFF_CTXT + HB)
#define OFF_DH0T (OFF_QT + HB)
#define OFF_DH1T (OFF_DH0T + 2*HB)
#define OFF_EH0T (OFF_DH1T + 2*HB)
#define OFF_EH1T (OFF_EH0T + 2*HB)
#define OFF_DC0  (OFF_EH1T + 2*HB)
#define OFF_DC1  (OFF_DC0 + HB)
#define OFF_EC0  (OFF_DC1 + HB)
#define OFF_EC1  (OFF_EC0 + HB)
#define ZERO_CNT (OFF_EC1 + HB)
#define OFF_XEMB ZERO_CNT
#define OFF_G0   (OFF_XEMB + T*B*H)     // [t][b][4H]
#define OFF_DOUT (OFF_G0 + T*B*4*H)     // [t][b][H]
#define OFF_NORM (OFF_DOUT + T*B*H)     // [5][t*32+b][H]  (batched logits input)
#define OFF_ERAW (OFF_NORM + 5*T*B*H)   // [b][t][H]
#define OFF_EOUT (OFF_ERAW + T*B*H)
#define OFF_KPRE (OFF_EOUT + T*B*H)     // [b*T+t][H]
#define OFF_PACK (OFF_KPRE + T*B*H)
#define PACK_SZ  (H*H*4)
#define N_PACK   7
#define BUF_TOTAL (OFF_PACK + (size_t)N_PACK*PACK_SZ)

__device__ float g_buf[BUF_TOTAL];
__device__ int   g_mask[B*T];
__device__ unsigned g_gen;
__device__ unsigned g_arr[NBLK];

// ---------------- low-level helpers ----------------
#define FMA2(a,x,w) asm("fma.rn.f32x2 %0, %1, %2, %0;" : "+l"(a) : "l"(x), "l"(w))
__device__ __forceinline__ ull pk2(float lo, float hi) {
    ull r; asm("mov.b64 %0, {%1,%2};" : "=l"(r) : "f"(lo), "f"(hi)); return r;
}
__device__ __forceinline__ float2 up2(ull v) {
    float2 f; asm("mov.b64 {%0,%1}, %2;" : "=f"(f.x), "=f"(f.y) : "l"(v)); return f;
}
__device__ __forceinline__ float ldcgf(const float* p) {
    float v; asm volatile("ld.global.cg.f32 %0, [%1];" : "=f"(v) : "l"(p)); return v;
}
__device__ __forceinline__ ull ldcg64(const ull* p) {
    ull v; asm volatile("ld.global.cg.b64 %0, [%1];" : "=l"(v) : "l"(p)); return v;
}
__device__ __forceinline__ ulonglong2 ldcgv2(const ulonglong2* p) {
    ulonglong2 v;
    asm volatile("ld.global.cg.v2.u64 {%0,%1}, [%2];" : "=l"(v.x), "=l"(v.y) : "l"(p));
    return v;
}
__device__ __forceinline__ void st_rel(unsigned* p, unsigned v) {
    asm volatile("st.release.gpu.global.u32 [%0], %1;" :: "l"(p), "r"(v) : "memory");
}
__device__ __forceinline__ unsigned ld_acq(const unsigned* p) {
    unsigned v; asm volatile("ld.acquire.gpu.global.u32 %0, [%1];" : "=r"(v) : "l"(p) : "memory"); return v;
}

// ---------------- grid barrier (monotonic generations; replay-safe) ----------------
__device__ __forceinline__ void gridbar(unsigned &mygen) {
    __syncthreads();
    mygen++;
    if (threadIdx.x == 0) st_rel(&g_arr[blockIdx.x], mygen);
    if (blockIdx.x == 0) {
        if (threadIdx.x < NBLK) {
            while ((int)(ld_acq(&g_arr[threadIdx.x]) - mygen) < 0) { }
        }
        __syncthreads();
        if (threadIdx.x == 0) st_rel(&g_gen, mygen);
    } else {
        if (threadIdx.x == 0) {
            while ((int)(ld_acq(&g_gen) - mygen) < 0) { }
        }
        __syncthreads();
    }
}

// ---------------- zero recurrent state ----------------
__global__ void k_zero() {
    int i = blockIdx.x * 256 + threadIdx.x;
    if (i < ZERO_CNT) g_buf[i] = 0.0f;
}

// ---------------- pack gate weights: per (j, kpair): i0,i1,f0,f1,g0,g1,o0,o1 ----------------
__global__ void k_pack2(const float* __restrict__ W, int ldw, float* __restrict__ P) {
    int kp = blockIdx.x * 128 + threadIdx.x;
    int j  = blockIdx.y;
    float* o = P + ((size_t)j*256 + kp)*8;
    #pragma unroll
    for (int g = 0; g < 4; g++) {
        o[g*2+0] = W[(size_t)(g*H + j) * ldw + 2*kp];
        o[g*2+1] = W[(size_t)(g*H + j) * ldw + 2*kp + 1];
    }
}

// ---------------- embedding gather ----------------
__global__ void k_gather(const int* __restrict__ inputs, const int* __restrict__ targets,
                         const float* __restrict__ emb, float* __restrict__ X,
                         int s, int is_dec) {
    int row = blockIdx.x;          // t*32 + b
    int t = row >> 5, b = row & 31;
    int tok;
    if (is_dec) {
        if (t == 0) tok = 1;
        else tok = (s == 0) ? inputs[b*192 + (t-1)] : targets[b*160 + (s-1)*32 + (t-1)];
    } else {
        tok = (s == 0) ? inputs[b*192 + t] : targets[b*160 + (s-1)*32 + t];
    }
    const float4* e = (const float4*)(emb + (size_t)tok * H);
    float4* o = (float4*)(X + (size_t)row * H);
    for (int i = threadIdx.x; i < H/4; i += 128) o[i] = e[i];
}

// ---------------- mask for next sentence ----------------
__global__ void k_maskk(const int* __restrict__ inputs, const int* __restrict__ targets, int s) {
    int b = threadIdx.x;
    if (b >= B) return;
    int seen = 0;
    for (int t = 0; t < T; t++) {
        g_mask[b*T + t] = seen;
        int tok = (s == 0) ? inputs[b*192 + t] : targets[b*160 + (s-1)*32 + t];
        if (tok == 2 || tok == 3) seen = 1;
    }
}

// ---------------- SGEMM 128x128 tile, 8x8 micro, double-buffered ----------------
// C[M,N] = A[M,512] @ W[N,ldw]^T + bias.  mode0: C[m*N+n]; mode1: logits remap.
__global__ __launch_bounds__(256) void k_gemm2(
    const float* __restrict__ A,
    const float* __restrict__ W, int ldw,
    const float* __restrict__ bias,
    float* __restrict__ C, int N, int mode)
{
    __shared__ float As[2][16][132];
    __shared__ float Bs[2][16][132];
    int tid = threadIdx.x;
    int m0 = blockIdx.y*128, n0 = blockIdx.x*128;
    int lr = tid >> 1, lc = (tid & 1)*8;
    int ty = tid >> 4, tx = tid & 15;
    float acc[8][8];
    #pragma unroll
    for (int i = 0; i < 8; i++)
        #pragma unroll
        for (int jq = 0; jq < 8; jq++) acc[i][jq] = 0.f;

    const float* Arow = A + (size_t)(m0 + lr) * 512;
    bool bvalid = (n0 + lr) < N;
    const float* Wrow = W + (size_t)(bvalid ? (n0 + lr) : 0) * ldw;
    float4 z4 = make_float4(0.f, 0.f, 0.f, 0.f);

    float4 pa0 = *(const float4*)(Arow + lc);
    float4 pa1 = *(const float4*)(Arow + lc + 4);
    float4 pb0 = bvalid ? *(const float4*)(Wrow + lc) : z4;
    float4 pb1 = bvalid ? *(const float4*)(Wrow + lc + 4) : z4;
    As[0][lc+0][lr]=pa0.x; As[0][lc+1][lr]=pa0.y; As[0][lc+2][lr]=pa0.z; As[0][lc+3][lr]=pa0.w;
    As[0][lc+4][lr]=pa1.x; As[0][lc+5][lr]=pa1.y; As[0][lc+6][lr]=pa1.z; As[0][lc+7][lr]=pa1.w;
    Bs[0][lc+0][lr]=pb0.x; Bs[0][lc+1][lr]=pb0.y; Bs[0][lc+2][lr]=pb0.z; Bs[0][lc+3][lr]=pb0.w;
    Bs[0][lc+4][lr]=pb1.x; Bs[0][lc+5][lr]=pb1.y; Bs[0][lc+6][lr]=pb1.z; Bs[0][lc+7][lr]=pb1.w;
    __syncthreads();

    int buf = 0;
    for (int k0 = 16; k0 <= 512; k0 += 16) {
        bool more = k0 < 512;
        if (more) {
            pa0 = *(const float4*)(Arow + k0 + lc);
            pa1 = *(const float4*)(Arow + k0 + lc + 4);
            pb0 = bvalid ? *(const float4*)(Wrow + k0 + lc) : z4;
            pb1 = bvalid ? *(const float4*)(Wrow + k0 + lc + 4) : z4;
        }
        #pragma unroll
        for (int k = 0; k < 16; k++) {
            float4 a0 = *(const float4*)&As[buf][k][ty*8];
            float4 a1 = *(const float4*)&As[buf][k][ty*8+4];
            float4 b0 = *(const float4*)&Bs[buf][k][tx*8];
            float4 b1 = *(const float4*)&Bs[buf][k][tx*8+4];
            float av[8] = {a0.x,a0.y,a0.z,a0.w,a1.x,a1.y,a1.z,a1.w};
            float bv[8] = {b0.x,b0.y,b0.z,b0.w,b1.x,b1.y,b1.z,b1.w};
            #pragma unroll
            for (int i = 0; i < 8; i++)
                #pragma unroll
                for (int jq = 0; jq < 8; jq++)
                    acc[i][jq] += av[i] * bv[jq];
        }
        if (more) {
            int nb = buf ^ 1;
            As[nb][lc+0][lr]=pa0.x; As[nb][lc+1][lr]=pa0.y; As[nb][lc+2][lr]=pa0.z; As[nb][lc+3][lr]=pa0.w;
            As[nb][lc+4][lr]=pa1.x; As[nb][lc+5][lr]=pa1.y; As[nb][lc+6][lr]=pa1.z; As[nb][lc+7][lr]=pa1.w;
            Bs[nb][lc+0][lr]=pb0.x; Bs[nb][lc+1][lr]=pb0.y; Bs[nb][lc+2][lr]=pb0.z; Bs[nb][lc+3][lr]=pb0.w;
            Bs[nb][lc+4][lr]=pb1.x; Bs[nb][lc+5][lr]=pb1.y; Bs[nb][lc+6][lr]=pb1.z; Bs[nb][lc+7][lr]=pb1.w;
        }
        __syncthreads();
        buf ^= 1;
    }
    #pragma unroll
    for (int i = 0; i < 8; i++) {
        int m = m0 + ty*8 + i;
        #pragma unroll
        for (int jq = 0; jq < 8; jq++) {
            int n = n0 + tx*8 + jq;
            if (n < N) {
                float v = acc[i][jq] + bias[n];
                if (mode == 0) C[(size_t)m*N + n] = v;
                else {
                    int ss = m >> 10, t = (m >> 5) & 31, b = m & 31;
                    C[(((size_t)b*5 + ss)*32 + t)*(size_t)V + n] = v;
                }
            }
        }
    }
}

// ---------------- layernorm ----------------
__global__ void k_ln(const float* __restrict__ in, float* __restrict__ out,
                     const float* __restrict__ g, const float* __restrict__ bb) {
    int row = blockIdx.x, tid = threadIdx.x;
    const float* x = in + (size_t)row * H;
    float v[4], s = 0.f;
    #pragma unroll
    for (int i = 0; i < 4; i++) { v[i] = x[tid + i*128]; s += v[i]; }
    __shared__ float rs[4];
    for (int o = 16; o; o >>= 1) s += __shfl_xor_sync(0xffffffffu, s, o);
    int warp = tid >> 5, lane = tid & 31;
    if (lane == 0) rs[warp] = s;
    __syncthreads();
    float mean = (rs[0] + rs[1] + rs[2] + rs[3]) / (float)H;
    __syncthreads();
    float s2 = 0.f;
    #pragma unroll
    for (int i = 0; i < 4; i++) { float d = v[i] - mean; s2 += d*d; }
    for (int o = 16; o; o >>= 1) s2 += __shfl_xor_sync(0xffffffffu, s2, o);
    if (lane == 0) rs[warp] = s2;
    __syncthreads();
    float var = (rs[0] + rs[1] + rs[2] + rs[3]) / (float)H;
    float inv = rsqrtf(var + 1e-5f);
    #pragma unroll
    for (int i = 0; i < 4; i++) {
        int c = tid + i*128;
        out[(size_t)row*H + c] = (v[i] - mean) * inv * g[c] + bb[c];
    }
}

// ---------------- cooperative chunk staging (32 k-pairs x 2 grps) ----------------
__device__ __forceinline__ void ld_chunk(const float* x0, const float* x1, int c, int tid,
                                         ulonglong2* r) {
    #pragma unroll
    for (int q = 0; q < 4; q++) {
        int idx = tid + q*256;
        const float* src = (idx >> 9) ? x1 : x0;
        int off = idx & 511;
        r[q] = ldcgv2((const ulonglong2*)src + (size_t)c*512 + off);
    }
}
__device__ __forceinline__ void st_chunk(ull* Xs, int b, int tid, const ulonglong2* r) {
    ulonglong2* dst = (ulonglong2*)(Xs + (size_t)b*2048);
    #pragma unroll
    for (int q = 0; q < 4; q++) dst[tid + q*256] = r[q];
}

// ---------------- fused LSTM phase: smem-staged x, smem weights, f32x2 ----------------
__device__ __forceinline__ void lstm_phase2(
    const ulonglong2* wv, int nkp,
    const float* x0, const float* x1, ull* Xs,
    const float* base, int base_vec,
    ull (*Red)[4][32],
    int tid, int jj, int grp, int lane, int j,
    float* cst, float* hT, float* extraBase, int extraStride)
{
    ull ai, af, ag, ao;
    float cold = 0.f;
    if (grp == 0) {
        cold = ldcgf(cst + (size_t)lane*H + j);
        float bi, bf, bg, bo;
        if (base_vec) { bi = base[j]; bf = base[H+j]; bg = base[2*H+j]; bo = base[3*H+j]; }
        else {
            const float* r = base + (size_t)lane * (4*H);
            bi = r[j]; bf = r[H+j]; bg = r[2*H+j]; bo = r[3*H+j];
        }
        ai = pk2(bi, 0.f); af = pk2(bf, 0.f); ag = pk2(bg, 0.f); ao = pk2(bo, 0.f);
    } else { ai = af = ag = ao = 0ull; }

    int nc = nkp >> 5;
    ulonglong2 r[4];
    ld_chunk(x0, x1, 0, tid, r);
    st_chunk(Xs, 0, tid, r);
    __syncthreads();
    for (int c = 0; c < nc; c++) {
        if (c + 1 < nc) ld_chunk(x0, x1, c+1, tid, r);
        const ull* xb = Xs + (size_t)(c & 1)*2048 + grp*1024 + lane;
        const ulonglong2* wc = wv + (size_t)c*64;
        #pragma unroll
        for (int kp = 0; kp < 32; kp++) {
            ull x2 = xb[kp*32];
            ulonglong2 wa = wc[kp*2];
            ulonglong2 wb = wc[kp*2 + 1];
            FMA2(ai, x2, wa.x); FMA2(af, x2, wa.y);
            FMA2(ag, x2, wb.x); FMA2(ao, x2, wb.y);
        }
        if (c + 1 < nc) st_chunk(Xs, (c+1) & 1, tid, r);
        __syncthreads();
    }
    if (grp == 1) {
        Red[jj][0][lane] = ai; Red[jj][1][lane] = af;
        Red[jj][2][lane] = ag; Red[jj][3][lane] = ao;
    }
    __syncthreads();
    if (grp == 0) {
        float2 A, R;
        A = up2(ai); R = up2(Red[jj][0][lane]); float gi = A.x + A.y + R.x + R.y;
        A = up2(af); R = up2(Red[jj][1][lane]); float gf = A.x + A.y + R.x + R.y;
        A = up2(ag); R = up2(Red[jj][2][lane]); float gg = A.x + A.y + R.x + R.y;
        A = up2(ao); R = up2(Red[jj][3][lane]); float go = A.x + A.y + R.x + R.y;
        float si = 1.f / (1.f + expf(-gi));
        float sf = 1.f / (1.f + expf(-gf));
        float so = 1.f / (1.f + expf(-go));
        float c2 = sf * cold + si * tanhf(gg);
        float h2 = so * tanhf(c2);
        cst[(size_t)lane*H + j] = c2;
        hT[((j>>1)*64) + lane*2 + (j&1)] = h2;
        if (extraBase) extraBase[(size_t)lane*extraStride + j] = h2;
    }
}

// ---------------- persistent decoder kernel ----------------
#define DEC_RED_OFF  131072
#define DEC_QS_OFF   (DEC_RED_OFF + 4096)
#define DEC_SC_OFF   (DEC_QS_OFF + 2048)
#define DEC_XS_OFF   (DEC_SC_OFF + 256)
#define SMEM_DEC     (DEC_XS_OFF + 32768)
__global__ __launch_bounds__(256, 1) void k_dec(
    const float* __restrict__ G0, const float* __restrict__ biasL1,
    const float* __restrict__ PC, const float* __restrict__ PH0,
    const float* __restrict__ PX1, const float* __restrict__ PH1,
    float* ctxT, float* h0T, float* h1T, float* c0, float* c1,
    float* qT, const float* __restrict__ attW, const float* __restrict__ attv,
    const float* __restrict__ Kpre, const float* __restrict__ Eout,
    float* Dout, int has_attn)
{
    extern __shared__ char smem[];
    float4* Wsm = (float4*)smem;
    ull (*Red)[4][32] = (ull (*)[4][32])(smem + DEC_RED_OFF);
    float* qs = (float*)(smem + DEC_QS_OFF);
    float* sc = (float*)(smem + DEC_SC_OFF);
    ull* Xs = (ull*)(smem + DEC_XS_OFF);

    int tid = threadIdx.x, warp = tid >> 5, lane = tid & 31;
    int jj = warp & 3, grp = warp >> 2;
    int bid = blockIdx.x;
    int j = bid*4 + jj;
    unsigned mygen = ld_acq(&g_gen);

    const float* srcs[4] = { PC, PH0, PX1, PH1 };
    for (int seg = 0; seg < 16; seg++) {
        int layer = seg >> 3, sjj = (seg >> 1) & 3, sgrp = seg & 1;
        const float4* s4 = (const float4*)srcs[layer*2 + sgrp] + (size_t)(4*bid + sjj)*512;
        float4* d4 = Wsm + ((size_t)((layer*4 + sjj)*2 + sgrp))*512;
        for (int i = tid; i < 512; i += 256) d4[i] = s4[i];
    }
    __syncthreads();

    const ulonglong2* wv0 = (const ulonglong2*)(Wsm + ((size_t)((0*4 + jj)*2 + grp))*512);
    const ulonglong2* wv1 = (const ulonglong2*)(Wsm + ((size_t)((1*4 + jj)*2 + grp))*512);

    for (int t = 0; t < T; t++) {
        int p = t & 1;
        float* h0r = h0T + p*HB;  float* h0w = h0T + (p^1)*HB;
        float* h1r = h1T + p*HB;  float* h1w = h1T + (p^1)*HB;

        if (has_attn) {
            // ---- Q phase (staged): q[b][j] = attW_q[j] . h1_prev[b] ----
            {
                ull aq = 0ull;
                const ull* wrow = (const ull*)(attW + (size_t)j * 1024) + grp*128;
                ulonglong2 r[4];
                const float* qx1 = h1r + 8192;
                ld_chunk(h1r, qx1, 0, tid, r);
                st_chunk(Xs, 0, tid, r);
                __syncthreads();
                for (int c = 0; c < 4; c++) {
                    if (c < 3) ld_chunk(h1r, qx1, c+1, tid, r);
                    const ull* xb = Xs + (size_t)(c & 1)*2048 + grp*1024 + lane;
                    const ull* wc = wrow + c*32;
                    #pragma unroll
                    for (int kk = 0; kk < 32; kk++) FMA2(aq, xb[kk*32], wc[kk]);
                    if (c < 3) st_chunk(Xs, (c+1) & 1, tid, r);
                    __syncthreads();
                }
                if (grp == 1) Red[jj][0][lane] = aq;
                __syncthreads();
                if (grp == 0) {
                    float2 A = up2(aq), R = up2(Red[jj][0][lane]);
                    qT[((j>>1)*64) + lane*2 + (j&1)] = A.x + A.y + R.x + R.y;
                }
            }
            gridbar(mygen);
            // ---- ATTN phase: blocks 0..31, b = bid ----
            if (bid < 32) {
                const int b = bid;
                const ull* qu = (const ull*)qT + b;
                for (int i = tid; i < 256; i += 256) ((ull*)qs)[i] = ldcg64(qu + (size_t)i*32);
                __syncthreads();
                for (int tt = warp; tt < T; tt += 8) {
                    if (g_mask[b*T + tt]) { if (lane == 0) sc[tt] = -1e9f; }
                    else {
                        float acc = 0.f;
                        const float* kr = Kpre + ((size_t)b*T + tt)*H;
                        #pragma unroll 4
                        for (int j2 = lane; j2 < H; j2 += 32) acc += tanhf(qs[j2] + kr[j2]) * attv[j2];
                        for (int o = 16; o; o >>= 1) acc += __shfl_xor_sync(0xffffffffu, acc, o);
                        if (lane == 0) sc[tt] = acc;
                    }
                }
                __syncthreads();
                if (tid < 32) {
                    float v = sc[tid], m = v;
                    for (int o = 16; o; o >>= 1) m = fmaxf(m, __shfl_xor_sync(0xffffffffu, m, o));
                    float e = expf(v - m), ss = e;
                    for (int o = 16; o; o >>= 1) ss += __shfl_xor_sync(0xffffffffu, ss, o);
                    sc[tid] = e / ss;
                }
                __syncthreads();
                #pragma unroll
                for (int h2 = 0; h2 < 2; h2++) {
                    int j2 = tid + h2*256;
                    float acc = 0.f;
                    const float* eo = Eout + (size_t)b*T*H + j2;
                    #pragma unroll
                    for (int t2 = 0; t2 < T; t2++) acc += sc[t2] * eo[(size_t)t2*H];
                    ctxT[((j2>>1)*64) + b*2 + (j2&1)] = acc;
                }
            }
            gridbar(mygen);
        }
        // ---- L0: grp0 src = ctx, grp1 src = h0 ----
        lstm_phase2(wv0, 256, ctxT, h0r, Xs, G0 + (size_t)t*B*4*H, 0,
                    Red, tid, jj, grp, lane, j, c0, h0w, (float*)0, 0);
        gridbar(mygen);
        // ---- L1: grp0 src = h0(new), grp1 src = h1 ----
        lstm_phase2(wv1, 256, h0w, h1r, Xs, biasL1, 1,
                    Red, tid, jj, grp, lane, j, c1, h1w, Dout + (size_t)t*B*H, H);
        gridbar(mygen);
    }
}

// ---------------- persistent encoder kernel ----------------
#define ENC_RED_OFF  98304
#define ENC_XS_OFF   (ENC_RED_OFF + 4096)
#define SMEM_ENC     (ENC_XS_OFF + 32768)
__global__ __launch_bounds__(256, 1) void k_enc(
    const float* __restrict__ G0, const float* __restrict__ biasL1,
    const float* __restrict__ PH0, const float* __restrict__ PX1, const float* __restrict__ PH1,
    float* h0T, float* h1T, float* c0, float* c1, float* Eraw)
{
    extern __shared__ char smem[];
    float4* Wsm = (float4*)smem;
    ull (*Red)[4][32] = (ull (*)[4][32])(smem + ENC_RED_OFF);
    ull* Xs = (ull*)(smem + ENC_XS_OFF);

    int tid = threadIdx.x, warp = tid >> 5, lane = tid & 31;
    int jj = warp & 3, grp = warp >> 2;
    int bid = blockIdx.x;
    int j = bid*4 + jj;
    unsigned mygen = ld_acq(&g_gen);

    for (int seg = 0; seg < 8; seg++) {
        int sjj = seg >> 1, sgrp = seg & 1;
        const float4* s4 = (const float4*)PH0 + (size_t)(4*bid + sjj)*512 + sgrp*256;
        float4* d4 = Wsm + (size_t)(sjj*2 + sgrp)*256;
        for (int i = tid; i < 256; i += 256) d4[i] = s4[i];
    }
    for (int seg = 0; seg < 8; seg++) {
        int sjj = seg >> 1, sgrp = seg & 1;
        const float4* s4 = (const float4*)(sgrp ? PH1 : PX1) + (size_t)(4*bid + sjj)*512;
        float4* d4 = Wsm + 2048 + (size_t)(sjj*2 + sgrp)*512;
        for (int i = tid; i < 512; i += 256) d4[i] = s4[i];
    }
    __syncthreads();

    const ulonglong2* wv0 = (const ulonglong2*)(Wsm + (size_t)(jj*2 + grp)*256);
    const ulonglong2* wv1 = (const ulonglong2*)(Wsm + 2048 + (size_t)(jj*2 + grp)*512);

    for (int t = 0; t < T; t++) {
        int p = t & 1;
        float* h0r = h0T + p*HB;  float* h0w = h0T + (p^1)*HB;
        float* h1r = h1T + p*HB;  float* h1w = h1T + (p^1)*HB;
        // ---- L0: single src h0, split by grp (128 kp each) ----
        lstm_phase2(wv0, 128, h0r, h0r + 8192, Xs, G0 + (size_t)t*B*4*H, 0,
                    Red, tid, jj, grp, lane, j, c0, h0w, (float*)0, 0);
        gridbar(mygen);
        // ---- L1 ----
        lstm_phase2(wv1, 256, h0w, h1r, Xs, biasL1, 1,
                    Red, tid, jj, grp, lane, j, c1, h1w, Eraw + (size_t)t*H, T*H);
        gridbar(mygen);
    }
}

// ---------------- host orchestration ----------------
extern "C" void kernel_launch(void* const* d_in, const int* in_sizes, int n_in,
                              void* d_out, int out_size) {
    const int*   inputs   = (const int*)d_in[0];
    const int*   targets  = (const int*)d_in[1];
    const float* enc_emb  = (const float*)d_in[2];
    const float* enc_Wih  = (const float*)d_in[3];
    const float* enc_Whh  = (const float*)d_in[4];
    const float* enc_bias = (const float*)d_in[5];
    const float* enc_ln_g = (const float*)d_in[6];
    const float* enc_ln_b = (const float*)d_in[7];
    const float* dec_emb  = (const float*)d_in[8];
    const float* att_W    = (const float*)d_in[9];
    const float* att_b    = (const float*)d_in[10];
    const float* att_v    = (const float*)d_in[11];
    const float* dec_Wih0 = (const float*)d_in[12];
    const float* dec_Wih1 = (const float*)d_in[13];
    const float* dec_Whh  = (const float*)d_in[14];
    const float* dec_bias = (const float*)d_in[15];
    const float* dec_ln_g = (const float*)d_in[16];
    const float* dec_ln_b = (const float*)d_in[17];
    const float* fc_W     = (const float*)d_in[18];
    const float* fc_b     = (const float*)d_in[19];
    float* out = (float*)d_out;

    float* buf = nullptr;
    cudaGetSymbolAddress((void**)&buf, g_buf);

    float* CtxT = buf + OFF_CTXT;
    float* QT   = buf + OFF_QT;
    float* DH0T = buf + OFF_DH0T;
    float* DH1T = buf + OFF_DH1T;
    float* EH0T = buf + OFF_EH0T;
    float* EH1T = buf + OFF_EH1T;
    float* DC0  = buf + OFF_DC0;
    float* DC1  = buf + OFF_DC1;
    float* EC0  = buf + OFF_EC0;
    float* EC1  = buf + OFF_EC1;
    float* Xemb = buf + OFF_XEMB;
    float* G0   = buf + OFF_G0;
    float* Dout = buf + OFF_DOUT;
    float* NormB= buf + OFF_NORM;
    float* Eraw = buf + OFF_ERAW;
    float* Eout = buf + OFF_EOUT;
    float* Kpre = buf + OFF_KPRE;
    float* P_DL0C = buf + OFF_PACK + 0ull*PACK_SZ;
    float* P_DL0H = buf + OFF_PACK + 1ull*PACK_SZ;
    float* P_DL1X = buf + OFF_PACK + 2ull*PACK_SZ;
    float* P_DL1H = buf + OFF_PACK + 3ull*PACK_SZ;
    float* P_EL0H = buf + OFF_PACK + 4ull*PACK_SZ;
    float* P_EL1X = buf + OFF_PACK + 5ull*PACK_SZ;
    float* P_EL1H = buf + OFF_PACK + 6ull*PACK_SZ;

    cudaFuncSetAttribute(k_dec, cudaFuncAttributeMaxDynamicSharedMemorySize, SMEM_DEC);
    cudaFuncSetAttribute(k_enc, cudaFuncAttributeMaxDynamicSharedMemorySize, SMEM_ENC);

    dim3 pg(2, 512);
    k_pack2<<<pg, 128>>>(dec_Wih0 + H,       2*H, P_DL0C);
    k_pack2<<<pg, 128>>>(dec_Whh,            H,   P_DL0H);
    k_pack2<<<pg, 128>>>(dec_Wih1,           H,   P_DL1X);
    k_pack2<<<pg, 128>>>(dec_Whh + 4*H*H,    H,   P_DL1H);
    k_pack2<<<pg, 128>>>(enc_Whh,            H,   P_EL0H);
    k_pack2<<<pg, 128>>>(enc_Wih + 4*H*H,    H,   P_EL1X);
    k_pack2<<<pg, 128>>>(enc_Whh + 4*H*H,    H,   P_EL1H);
    k_zero<<<(ZERO_CNT + 255)/256, 256>>>();

    for (int s = 0; s < NS; s++) {
        // ---- decoder ----
        k_gather<<<T*B, 128>>>(inputs, targets, dec_emb, Xemb, s, 1);
        k_gemm2<<<dim3(16, 8), 256>>>(Xemb, dec_Wih0, 2*H, dec_bias, G0, 4*H, 0);
        k_dec<<<NBLK, 256, SMEM_DEC>>>(G0, dec_bias + 4*H,
                                       P_DL0C, P_DL0H, P_DL1X, P_DL1H,
                                       CtxT, DH0T, DH1T, DC0, DC1,
                                       QT, att_W, att_v, Kpre, Eout, Dout,
                                       (s > 0) ? 1 : 0);
        if (s > 0)
            k_ln<<<T*B, 128>>>(Dout, NormB + (size_t)(s-1)*T*B*H, dec_ln_g, dec_ln_b);
        if (s < NS - 1) {
            k_maskk<<<1, 32>>>(inputs, targets, s);
            // ---- encoder ----
            k_gather<<<T*B, 128>>>(inputs, targets, enc_emb, Xemb, s, 0);
            k_gemm2<<<dim3(16, 8), 256>>>(Xemb, enc_Wih, H, enc_bias, G0, 4*H, 0);
            k_enc<<<NBLK, 256, SMEM_ENC>>>(G0, enc_bias + 4*H,
                                           P_EL0H, P_EL1X, P_EL1H,
                                           EH0T, EH1T, EC0, EC1, Eraw);
            k_ln<<<T*B, 128>>>(Eraw, Eout, enc_ln_g, enc_ln_b);
            k_gemm2<<<dim3(4, 8), 256>>>(Eout, att_W + H, 2*H, att_b, Kpre, H, 0);
        }
    }
    // ---- batched logits: [5120, 512] @ fc_W^T -> out ----
    k_gemm2<<<dim3((V + 127)/128, 40), 256>>>(NormB, fc_W, H, fc_b, out, V, 1);
}